// round 1
// baseline (speedup 1.0000x reference)
#include <cuda_runtime.h>
#include <cuda_bf16.h>
#include <math.h>

// ---------------------------------------------------------------------------
// Problem constants
// ---------------------------------------------------------------------------
#define NSEQ 2048
#define DMODEL 1024
#define NHEAD 16
#define HDIM 64
#define DFF 4096
#define NOFF 44
#define D3 (3 * DMODEL)

__constant__ int c_offs[NOFF] = {
    0,1,2,3,4,5,6,7,8,9,10,11,12,13,14,15,16,17,18,19,20,21,22,23,24,25,26,27,
    28,29,30,31,32,48,64,96,128,192,256,384,512,768,1024,1536};

// ---------------------------------------------------------------------------
// Scratch (no allocation allowed -> __device__ globals)
// ---------------------------------------------------------------------------
__device__ float g_xn [NSEQ * DMODEL];   // LN1(x)
__device__ float g_qkv[NSEQ * D3];       // qkv projection
__device__ float g_gate[NSEQ * DMODEL];  // sigmoid(xn@gate_w+gate_b)
__device__ float g_y  [NSEQ * DMODEL];   // attention out * gate
__device__ float g_x1 [NSEQ * DMODEL];   // x + attn_out
__device__ float g_xn2[NSEQ * DMODEL];   // LN2(x1)
__device__ float g_h  [NSEQ * DFF];      // gelu(fc1)

// ---------------------------------------------------------------------------
// LayerNorm: one block per row, 256 threads, 4 floats/thread (D=1024)
// ---------------------------------------------------------------------------
__global__ void ln_kernel(const float* __restrict__ x,
                          const float* __restrict__ g,
                          const float* __restrict__ b,
                          float* __restrict__ out) {
    int row = blockIdx.x;
    int tid = threadIdx.x;
    const float4* xr = (const float4*)(x + (size_t)row * DMODEL);
    float4 v = xr[tid];
    float s  = v.x + v.y + v.z + v.w;
    float sq = v.x * v.x + v.y * v.y + v.z * v.z + v.w * v.w;
    // warp reduce
    #pragma unroll
    for (int o = 16; o > 0; o >>= 1) {
        s  += __shfl_xor_sync(0xffffffffu, s,  o);
        sq += __shfl_xor_sync(0xffffffffu, sq, o);
    }
    __shared__ float sh[16];
    int wid = tid >> 5, lane = tid & 31;
    if (lane == 0) { sh[wid] = s; sh[wid + 8] = sq; }
    __syncthreads();
    float ts = 0.f, tq = 0.f;
    #pragma unroll
    for (int w = 0; w < 8; w++) { ts += sh[w]; tq += sh[w + 8]; }
    float mu  = ts * (1.0f / DMODEL);
    float var = tq * (1.0f / DMODEL) - mu * mu;
    var = var > 0.f ? var : 0.f;
    float rstd = rsqrtf(var + 1e-5f);

    float4 gv = ((const float4*)g)[tid];
    float4 bv = ((const float4*)b)[tid];
    float4 ov;
    ov.x = (v.x - mu) * rstd * gv.x + bv.x;
    ov.y = (v.y - mu) * rstd * gv.y + bv.y;
    ov.z = (v.z - mu) * rstd * gv.z + bv.z;
    ov.w = (v.w - mu) * rstd * gv.w + bv.w;
    ((float4*)(out + (size_t)row * DMODEL))[tid] = ov;
}

// ---------------------------------------------------------------------------
// SGEMM: C[M,N] = A[M,K] @ B[K,N] + bias, epilogue per EPI.
//   EPI 0: + bias
//   EPI 1: sigmoid(+bias)
//   EPI 2: + bias + res
//   EPI 3: gelu_exact(+bias)
// Tiles: BM=64, BN=128, BK=8, 128 threads, 8x8 per-thread microtile.
// All dims divide tiles exactly (M=2048, N in {1024,3072,4096}, K in {1024,4096}).
// ---------------------------------------------------------------------------
template <int EPI>
__global__ void sgemm_kernel(const float* __restrict__ A,
                             const float* __restrict__ B,
                             const float* __restrict__ bias,
                             const float* __restrict__ res,
                             float* __restrict__ C,
                             int M, int N, int K) {
    __shared__ float As[8][64];
    __shared__ float Bs[8][128];

    int tid = threadIdx.x;            // 0..127
    int tx = tid & 15;                // 0..15 -> 8 cols each
    int ty = tid >> 4;                // 0..7  -> 8 rows each
    int rowBase = blockIdx.y * 64;
    int colBase = blockIdx.x * 128;
    int rowC = rowBase + ty * 8;
    int colC = colBase + tx * 8;

    int aRow = tid >> 1;              // 0..63
    int aCol = (tid & 1) * 4;         // 0 or 4
    int bRow = tid >> 4;              // 0..7
    int bCol = (tid & 15) * 8;        // 0..120

    const float* Aptr = A + (size_t)(rowBase + aRow) * K + aCol;
    const float* Bptr = B + (size_t)bRow * N + colBase + bCol;

    float acc[8][8];
    #pragma unroll
    for (int i = 0; i < 8; i++)
        #pragma unroll
        for (int j = 0; j < 8; j++) acc[i][j] = 0.f;

    for (int k0 = 0; k0 < K; k0 += 8) {
        float4 av = *(const float4*)(Aptr + k0);
        As[aCol + 0][aRow] = av.x;
        As[aCol + 1][aRow] = av.y;
        As[aCol + 2][aRow] = av.z;
        As[aCol + 3][aRow] = av.w;
        float4 bv0 = *(const float4*)(Bptr + (size_t)k0 * N);
        float4 bv1 = *(const float4*)(Bptr + (size_t)k0 * N + 4);
        *(float4*)&Bs[bRow][bCol]     = bv0;
        *(float4*)&Bs[bRow][bCol + 4] = bv1;
        __syncthreads();

        #pragma unroll
        for (int k = 0; k < 8; k++) {
            float a[8], bb[8];
            float4 a0 = *(float4*)&As[k][ty * 8];
            float4 a1 = *(float4*)&As[k][ty * 8 + 4];
            a[0]=a0.x; a[1]=a0.y; a[2]=a0.z; a[3]=a0.w;
            a[4]=a1.x; a[5]=a1.y; a[6]=a1.z; a[7]=a1.w;
            float4 b0 = *(float4*)&Bs[k][tx * 8];
            float4 b1 = *(float4*)&Bs[k][tx * 8 + 4];
            bb[0]=b0.x; bb[1]=b0.y; bb[2]=b0.z; bb[3]=b0.w;
            bb[4]=b1.x; bb[5]=b1.y; bb[6]=b1.z; bb[7]=b1.w;
            #pragma unroll
            for (int i = 0; i < 8; i++)
                #pragma unroll
                for (int j = 0; j < 8; j++)
                    acc[i][j] = fmaf(a[i], bb[j], acc[i][j]);
        }
        __syncthreads();
    }

    float bs[8];
    #pragma unroll
    for (int j = 0; j < 8; j++) bs[j] = bias[colC + j];

    #pragma unroll
    for (int i = 0; i < 8; i++) {
        float out[8];
        #pragma unroll
        for (int j = 0; j < 8; j++) {
            float v = acc[i][j] + bs[j];
            if (EPI == 1) {
                v = 1.0f / (1.0f + expf(-v));
            } else if (EPI == 3) {
                v = 0.5f * v * (1.0f + erff(v * 0.70710678118654752f));
            }
            out[j] = v;
        }
        size_t off = (size_t)(rowC + i) * N + colC;
        if (EPI == 2) {
            float4 r0 = *(const float4*)(res + off);
            float4 r1 = *(const float4*)(res + off + 4);
            out[0] += r0.x; out[1] += r0.y; out[2] += r0.z; out[3] += r0.w;
            out[4] += r1.x; out[5] += r1.y; out[6] += r1.z; out[7] += r1.w;
        }
        float4 o0 = make_float4(out[0], out[1], out[2], out[3]);
        float4 o1 = make_float4(out[4], out[5], out[6], out[7]);
        *(float4*)(C + off)     = o0;
        *(float4*)(C + off + 4) = o1;
    }
}

// ---------------------------------------------------------------------------
// Offset attention. One warp per (n, h).
// qkv row layout: [ q(1024) | k(1024) | v(1024) ], head h at cols h*64..h*64+63.
// Lane l owns HD components 2l, 2l+1 (float2).
// Scores kept as: sLo in lane o (o<32), sHi in lane o-32 (o>=32, lanes 0..11).
// y = (attn_out * gate)
// ---------------------------------------------------------------------------
__global__ void attn_kernel(const float* __restrict__ qkv,
                            const float* __restrict__ gate,
                            const float* __restrict__ pos_bias,
                            float* __restrict__ y) {
    int warp = (blockIdx.x * blockDim.x + threadIdx.x) >> 5;
    int lane = threadIdx.x & 31;
    int n = warp >> 4;      // 0..2047
    int h = warp & 15;      // 0..15

    const float* qrow  = qkv + (size_t)n * D3 + h * HDIM;
    const float* kbase = qkv + DMODEL + h * HDIM;
    const float* vbase = qkv + 2 * DMODEL + h * HDIM;

    float2 q = *(const float2*)(qrow + 2 * lane);

    const float scale = 0.125f;   // 64^-0.5
    float sLo = -INFINITY, sHi = -INFINITY;
    float mx = -INFINITY;

    #pragma unroll
    for (int o = 0; o < NOFF; o++) {
        int delta = c_offs[o];
        float s;
        if (delta <= n) {
            float2 kk = *(const float2*)(kbase + (size_t)(n - delta) * D3 + 2 * lane);
            s = q.x * kk.x + q.y * kk.y;
            #pragma unroll
            for (int w = 16; w > 0; w >>= 1)
                s += __shfl_xor_sync(0xffffffffu, s, w);
            s = s * scale + pos_bias[o * NHEAD + h];
        } else {
            s = -INFINITY;
        }
        mx = fmaxf(mx, s);
        if (o < 32) { if (lane == o) sLo = s; }
        else        { if (lane == o - 32) sHi = s; }
    }

    float eLo = expf(sLo - mx);                       // -inf -> 0
    float eHi = (lane < NOFF - 32) ? expf(sHi - mx) : 0.f;
    float denom = eLo + eHi;
    #pragma unroll
    for (int w = 16; w > 0; w >>= 1)
        denom += __shfl_xor_sync(0xffffffffu, denom, w);
    float inv = 1.0f / denom;

    float2 acc = make_float2(0.f, 0.f);
    #pragma unroll
    for (int o = 0; o < NOFF; o++) {
        int delta = c_offs[o];
        float aw = (o < 32) ? __shfl_sync(0xffffffffu, eLo, o)
                            : __shfl_sync(0xffffffffu, eHi, o - 32);
        if (delta <= n) {
            float2 vv = *(const float2*)(vbase + (size_t)(n - delta) * D3 + 2 * lane);
            acc.x = fmaf(aw, vv.x, acc.x);
            acc.y = fmaf(aw, vv.y, acc.y);
        }
    }
    acc.x *= inv;
    acc.y *= inv;

    size_t yoff = (size_t)n * DMODEL + h * HDIM + 2 * lane;
    float2 g2 = *(const float2*)(gate + yoff);
    float2 out = make_float2(acc.x * g2.x, acc.y * g2.y);
    *(float2*)(y + yoff) = out;
}

// ---------------------------------------------------------------------------
// Launch
// ---------------------------------------------------------------------------
static float* s_xn  = nullptr;
static float* s_qkv = nullptr;
static float* s_gate= nullptr;
static float* s_y   = nullptr;
static float* s_x1  = nullptr;
static float* s_xn2 = nullptr;
static float* s_h   = nullptr;

extern "C" void kernel_launch(void* const* d_in, const int* in_sizes, int n_in,
                              void* d_out, int out_size) {
    if (!s_xn) {
        cudaGetSymbolAddress((void**)&s_xn,  g_xn);
        cudaGetSymbolAddress((void**)&s_qkv, g_qkv);
        cudaGetSymbolAddress((void**)&s_gate,g_gate);
        cudaGetSymbolAddress((void**)&s_y,   g_y);
        cudaGetSymbolAddress((void**)&s_x1,  g_x1);
        cudaGetSymbolAddress((void**)&s_xn2, g_xn2);
        cudaGetSymbolAddress((void**)&s_h,   g_h);
    }

    const float* x      = (const float*)d_in[0];
    const float* ln1_g  = (const float*)d_in[1];
    const float* ln1_b  = (const float*)d_in[2];
    const float* qkv_w  = (const float*)d_in[3];
    const float* qkv_b  = (const float*)d_in[4];
    const float* gate_w = (const float*)d_in[5];
    const float* gate_b = (const float*)d_in[6];
    const float* out_w  = (const float*)d_in[7];
    const float* out_b  = (const float*)d_in[8];
    const float* pbias  = (const float*)d_in[9];
    const float* ln2_g  = (const float*)d_in[10];
    const float* ln2_b  = (const float*)d_in[11];
    const float* fc1_w  = (const float*)d_in[12];
    const float* fc1_b  = (const float*)d_in[13];
    const float* fc2_w  = (const float*)d_in[14];
    const float* fc2_b  = (const float*)d_in[15];
    float* out = (float*)d_out;

    // 1) LN1
    ln_kernel<<<NSEQ, 256>>>(x, ln1_g, ln1_b, s_xn);
    // 2) qkv = xn @ qkv_w + qkv_b
    sgemm_kernel<0><<<dim3(D3 / 128, NSEQ / 64), 128>>>(
        s_xn, qkv_w, qkv_b, nullptr, s_qkv, NSEQ, D3, DMODEL);
    // 3) gate = sigmoid(xn @ gate_w + gate_b)
    sgemm_kernel<1><<<dim3(DMODEL / 128, NSEQ / 64), 128>>>(
        s_xn, gate_w, gate_b, nullptr, s_gate, NSEQ, DMODEL, DMODEL);
    // 4) attention (+ gate multiply)
    attn_kernel<<<(NSEQ * NHEAD * 32) / 256, 256>>>(s_qkv, s_gate, pbias, s_y);
    // 5) x1 = x + y @ out_w + out_b
    sgemm_kernel<2><<<dim3(DMODEL / 128, NSEQ / 64), 128>>>(
        s_y, out_w, out_b, x, s_x1, NSEQ, DMODEL, DMODEL);
    // 6) LN2
    ln_kernel<<<NSEQ, 256>>>(s_x1, ln2_g, ln2_b, s_xn2);
    // 7) h = gelu(xn2 @ fc1_w + fc1_b)
    sgemm_kernel<3><<<dim3(DFF / 128, NSEQ / 64), 128>>>(
        s_xn2, fc1_w, fc1_b, nullptr, s_h, NSEQ, DFF, DMODEL);
    // 8) out = x1 + h @ fc2_w + fc2_b
    sgemm_kernel<2><<<dim3(DMODEL / 128, NSEQ / 64), 128>>>(
        s_h, fc2_w, fc2_b, s_x1, out, NSEQ, DMODEL, DFF);
}

// round 2
// speedup vs baseline: 2.6948x; 2.6948x over previous
#include <cuda_runtime.h>
#include <cuda_bf16.h>
#include <math.h>
#include <stdint.h>

// ---------------------------------------------------------------------------
// Problem constants
// ---------------------------------------------------------------------------
#define NSEQ 2048
#define DMODEL 1024
#define NHEAD 16
#define HDIM 64
#define DFF 4096
#define NOFF 44
#define D3 (3 * DMODEL)

__constant__ int c_offs[NOFF] = {
    0,1,2,3,4,5,6,7,8,9,10,11,12,13,14,15,16,17,18,19,20,21,22,23,24,25,26,27,
    28,29,30,31,32,48,64,96,128,192,256,384,512,768,1024,1536};

// ---------------------------------------------------------------------------
// Scratch (__device__ globals; no allocation allowed)
// ---------------------------------------------------------------------------
__device__ float g_xn [NSEQ * DMODEL];   // LN1(x), tf32-rounded
__device__ float g_qkv[NSEQ * D3];       // qkv projection (fp32)
__device__ float g_gate[NSEQ * DMODEL];  // sigmoid gate (fp32)
__device__ float g_y  [NSEQ * DMODEL];   // attn*gate, tf32-rounded
__device__ float g_x1 [NSEQ * DMODEL];   // x + attn_out (fp32)
__device__ float g_xn2[NSEQ * DMODEL];   // LN2(x1), tf32-rounded
__device__ float g_h  [NSEQ * DFF];      // gelu(fc1), tf32-rounded
// tf32-rounded weights
__device__ float g_wqkv [DMODEL * D3];
__device__ float g_wgate[DMODEL * DMODEL];
__device__ float g_wout [DMODEL * DMODEL];
__device__ float g_wfc1 [DMODEL * DFF];
__device__ float g_wfc2 [DFF * DMODEL];

// ---------------------------------------------------------------------------
// tf32 round-to-nearest helper
// ---------------------------------------------------------------------------
__device__ __forceinline__ float f2tf(float x) {
    uint32_t u;
    asm("cvt.rna.tf32.f32 %0, %1;" : "=r"(u) : "f"(x));
    return __uint_as_float(u);
}

// ---------------------------------------------------------------------------
// Elementwise tf32-round (weights)
// ---------------------------------------------------------------------------
__global__ void cvt_kernel(const float4* __restrict__ in, float4* __restrict__ out, int n4) {
    int i = blockIdx.x * 256 + threadIdx.x;
    if (i < n4) {
        float4 v = in[i];
        v.x = f2tf(v.x); v.y = f2tf(v.y); v.z = f2tf(v.z); v.w = f2tf(v.w);
        out[i] = v;
    }
}

// ---------------------------------------------------------------------------
// LayerNorm: one block per row, 256 threads, output tf32-rounded
// ---------------------------------------------------------------------------
__global__ void ln_kernel(const float* __restrict__ x,
                          const float* __restrict__ g,
                          const float* __restrict__ b,
                          float* __restrict__ out) {
    int row = blockIdx.x;
    int tid = threadIdx.x;
    const float4* xr = (const float4*)(x + (size_t)row * DMODEL);
    float4 v = xr[tid];
    float s  = v.x + v.y + v.z + v.w;
    float sq = v.x * v.x + v.y * v.y + v.z * v.z + v.w * v.w;
    #pragma unroll
    for (int o = 16; o > 0; o >>= 1) {
        s  += __shfl_xor_sync(0xffffffffu, s,  o);
        sq += __shfl_xor_sync(0xffffffffu, sq, o);
    }
    __shared__ float sh[16];
    int wid = tid >> 5, lane = tid & 31;
    if (lane == 0) { sh[wid] = s; sh[wid + 8] = sq; }
    __syncthreads();
    float ts = 0.f, tq = 0.f;
    #pragma unroll
    for (int w = 0; w < 8; w++) { ts += sh[w]; tq += sh[w + 8]; }
    float mu  = ts * (1.0f / DMODEL);
    float var = tq * (1.0f / DMODEL) - mu * mu;
    var = var > 0.f ? var : 0.f;
    float rstd = rsqrtf(var + 1e-5f);

    float4 gv = ((const float4*)g)[tid];
    float4 bv = ((const float4*)b)[tid];
    float4 ov;
    ov.x = f2tf((v.x - mu) * rstd * gv.x + bv.x);
    ov.y = f2tf((v.y - mu) * rstd * gv.y + bv.y);
    ov.z = f2tf((v.z - mu) * rstd * gv.z + bv.z);
    ov.w = f2tf((v.w - mu) * rstd * gv.w + bv.w);
    ((float4*)(out + (size_t)row * DMODEL))[tid] = ov;
}

// ---------------------------------------------------------------------------
// tf32 tensor-core GEMM: C[M,N] = A[M,K] @ B[K,N] (+bias, epilogue EPI)
//   EPI 0: +bias | 1: sigmoid | 2: +bias+res | 3: gelu_exact
//   CVT: round output to tf32 (when output feeds another GEMM)
// Tile BM x 128 x 16, 256 threads (8 warps, 2x4), mma.m16n8k8, cp.async
// double buffer. All problem dims divide the tiles exactly.
// ---------------------------------------------------------------------------
#define CPA16(dst, src) \
    asm volatile("cp.async.cg.shared.global [%0], [%1], 16;\n" :: "r"(dst), "l"(src))

template <int BM, int EPI, bool CVT>
__global__ void __launch_bounds__(256, 2)
tgemm(const float* __restrict__ A, const float* __restrict__ B,
      const float* __restrict__ bias, const float* __restrict__ res,
      float* __restrict__ C, int N, int K) {
    constexpr int BN = 128, BK = 16;
    constexpr int AS = BK + 4;    // 20 floats, conflict-free frag loads
    constexpr int BS = BN + 8;    // 136 floats, conflict-free frag loads
    constexpr int MI = BM / 32;   // m16 tiles per warp

    __shared__ __align__(16) float smA[2][BM * AS];
    __shared__ __align__(16) float smB[2][BK * BS];

    const int tid  = threadIdx.x;
    const int warp = tid >> 5, lane = tid & 31;
    const int g    = lane >> 2, t4 = lane & 3;
    const int warpM = (warp >> 2) * (BM / 2);
    const int warpN = (warp & 3) * 32;
    const int rowBase = blockIdx.y * BM;
    const int colBase = blockIdx.x * BN;

    const int aRow = tid >> 2;            // 0..63
    const int aCol = (tid & 3) * 4;       // 0,4,8,12
    const int bRow = tid >> 5;            // 0..7
    const int bCol = (tid & 31) * 4;      // 0..124

    const float* Agp = A + (size_t)(rowBase + aRow) * K + aCol;
    const float* Bgp = B + (size_t)bRow * N + colBase + bCol;

    const uint32_t sa = (uint32_t)__cvta_generic_to_shared(&smA[0][0]);
    const uint32_t sb = (uint32_t)__cvta_generic_to_shared(&smB[0][0]);
    constexpr uint32_t ABUF = BM * AS * 4;
    constexpr uint32_t BBUF = BK * BS * 4;

    float acc[MI][4][4];
    #pragma unroll
    for (int mi = 0; mi < MI; mi++)
        #pragma unroll
        for (int ni = 0; ni < 4; ni++)
            #pragma unroll
            for (int r = 0; r < 4; r++) acc[mi][ni][r] = 0.f;

    const uint32_t daBase = sa + (aRow * AS + aCol) * 4;
    const uint32_t dbBase = sb + (bRow * BS + bCol) * 4;

    // prologue: tile 0
    {
        #pragma unroll
        for (int i = 0; i < BM / 64; i++)
            CPA16(daBase + i * 64 * AS * 4, Agp + (size_t)i * 64 * K);
        #pragma unroll
        for (int i = 0; i < 2; i++)
            CPA16(dbBase + i * 8 * BS * 4, Bgp + (size_t)i * 8 * N);
        asm volatile("cp.async.commit_group;\n");
    }

    const int KT = K / BK;
    for (int kt = 0; kt < KT; kt++) {
        const int buf = kt & 1;
        if (kt + 1 < KT) {
            const int nb = buf ^ 1;
            const float* pa = Agp + (kt + 1) * BK;
            #pragma unroll
            for (int i = 0; i < BM / 64; i++)
                CPA16(daBase + nb * ABUF + i * 64 * AS * 4, pa + (size_t)i * 64 * K);
            const float* pb = Bgp + (size_t)(kt + 1) * BK * N;
            #pragma unroll
            for (int i = 0; i < 2; i++)
                CPA16(dbBase + nb * BBUF + i * 8 * BS * 4, pb + (size_t)i * 8 * N);
            asm volatile("cp.async.commit_group;\n");
            asm volatile("cp.async.wait_group 1;\n");
        } else {
            asm volatile("cp.async.wait_group 0;\n");
        }
        __syncthreads();

        const uint32_t* pA = (const uint32_t*)&smA[buf][0];
        const uint32_t* pB = (const uint32_t*)&smB[buf][0];
        #pragma unroll
        for (int ks = 0; ks < 2; ks++) {
            uint32_t af[MI][4], bf[4][2];
            #pragma unroll
            for (int mi = 0; mi < MI; mi++) {
                int m = warpM + mi * 16 + g;
                af[mi][0] = pA[(size_t)m * AS + ks * 8 + t4];
                af[mi][1] = pA[(size_t)(m + 8) * AS + ks * 8 + t4];
                af[mi][2] = pA[(size_t)m * AS + ks * 8 + t4 + 4];
                af[mi][3] = pA[(size_t)(m + 8) * AS + ks * 8 + t4 + 4];
            }
            #pragma unroll
            for (int ni = 0; ni < 4; ni++) {
                int n = warpN + ni * 8 + g;
                bf[ni][0] = pB[(size_t)(ks * 8 + t4) * BS + n];
                bf[ni][1] = pB[(size_t)(ks * 8 + t4 + 4) * BS + n];
            }
            #pragma unroll
            for (int mi = 0; mi < MI; mi++)
                #pragma unroll
                for (int ni = 0; ni < 4; ni++)
                    asm volatile(
                        "mma.sync.aligned.m16n8k8.row.col.f32.tf32.tf32.f32 "
                        "{%0,%1,%2,%3}, {%4,%5,%6,%7}, {%8,%9}, {%0,%1,%2,%3};\n"
                        : "+f"(acc[mi][ni][0]), "+f"(acc[mi][ni][1]),
                          "+f"(acc[mi][ni][2]), "+f"(acc[mi][ni][3])
                        : "r"(af[mi][0]), "r"(af[mi][1]), "r"(af[mi][2]), "r"(af[mi][3]),
                          "r"(bf[ni][0]), "r"(bf[ni][1]));
        }
        __syncthreads();
    }

    // epilogue
    #pragma unroll
    for (int mi = 0; mi < MI; mi++) {
        #pragma unroll
        for (int ni = 0; ni < 4; ni++) {
            int row = rowBase + warpM + mi * 16 + g;
            int col = colBase + warpN + ni * 8 + t4 * 2;
            float b0 = bias[col], b1 = bias[col + 1];
            #pragma unroll
            for (int half = 0; half < 2; half++) {
                int r = row + half * 8;
                float vx = acc[mi][ni][half * 2 + 0] + b0;
                float vy = acc[mi][ni][half * 2 + 1] + b1;
                if (EPI == 1) {
                    vx = 1.0f / (1.0f + expf(-vx));
                    vy = 1.0f / (1.0f + expf(-vy));
                } else if (EPI == 3) {
                    vx = 0.5f * vx * (1.0f + erff(vx * 0.70710678118654752f));
                    vy = 0.5f * vy * (1.0f + erff(vy * 0.70710678118654752f));
                }
                if (EPI == 2) {
                    float2 rr = *(const float2*)(res + (size_t)r * N + col);
                    vx += rr.x; vy += rr.y;
                }
                if (CVT) { vx = f2tf(vx); vy = f2tf(vy); }
                float2 o = make_float2(vx, vy);
                *(float2*)(C + (size_t)r * N + col) = o;
            }
        }
    }
}

// ---------------------------------------------------------------------------
// Offset attention. One warp per (n, h). Output tf32-rounded (feeds out_w GEMM)
// ---------------------------------------------------------------------------
__global__ void attn_kernel(const float* __restrict__ qkv,
                            const float* __restrict__ gate,
                            const float* __restrict__ pos_bias,
                            float* __restrict__ y) {
    int warp = (blockIdx.x * blockDim.x + threadIdx.x) >> 5;
    int lane = threadIdx.x & 31;
    int n = warp >> 4;
    int h = warp & 15;

    const float* qrow  = qkv + (size_t)n * D3 + h * HDIM;
    const float* kbase = qkv + DMODEL + h * HDIM;
    const float* vbase = qkv + 2 * DMODEL + h * HDIM;

    float2 q = *(const float2*)(qrow + 2 * lane);

    const float scale = 0.125f;
    float sLo = -INFINITY, sHi = -INFINITY;
    float mx = -INFINITY;

    #pragma unroll
    for (int o = 0; o < NOFF; o++) {
        int delta = c_offs[o];
        float s;
        if (delta <= n) {
            float2 kk = *(const float2*)(kbase + (size_t)(n - delta) * D3 + 2 * lane);
            s = q.x * kk.x + q.y * kk.y;
            #pragma unroll
            for (int w = 16; w > 0; w >>= 1)
                s += __shfl_xor_sync(0xffffffffu, s, w);
            s = s * scale + pos_bias[o * NHEAD + h];
        } else {
            s = -INFINITY;
        }
        mx = fmaxf(mx, s);
        if (o < 32) { if (lane == o) sLo = s; }
        else        { if (lane == o - 32) sHi = s; }
    }

    float eLo = expf(sLo - mx);
    float eHi = (lane < NOFF - 32) ? expf(sHi - mx) : 0.f;
    float denom = eLo + eHi;
    #pragma unroll
    for (int w = 16; w > 0; w >>= 1)
        denom += __shfl_xor_sync(0xffffffffu, denom, w);
    float inv = 1.0f / denom;

    float2 acc = make_float2(0.f, 0.f);
    #pragma unroll
    for (int o = 0; o < NOFF; o++) {
        int delta = c_offs[o];
        float aw = (o < 32) ? __shfl_sync(0xffffffffu, eLo, o)
                            : __shfl_sync(0xffffffffu, eHi, o - 32);
        if (delta <= n) {
            float2 vv = *(const float2*)(vbase + (size_t)(n - delta) * D3 + 2 * lane);
            acc.x = fmaf(aw, vv.x, acc.x);
            acc.y = fmaf(aw, vv.y, acc.y);
        }
    }
    acc.x *= inv;
    acc.y *= inv;

    size_t yoff = (size_t)n * DMODEL + h * HDIM + 2 * lane;
    float2 g2 = *(const float2*)(gate + yoff);
    float2 out = make_float2(f2tf(acc.x * g2.x), f2tf(acc.y * g2.y));
    *(float2*)(y + yoff) = out;
}

// ---------------------------------------------------------------------------
// Launch
// ---------------------------------------------------------------------------
extern "C" void kernel_launch(void* const* d_in, const int* in_sizes, int n_in,
                              void* d_out, int out_size) {
    float *s_xn, *s_qkv, *s_gate, *s_y, *s_x1, *s_xn2, *s_h;
    float *s_wqkv, *s_wgate, *s_wout, *s_wfc1, *s_wfc2;
    cudaGetSymbolAddress((void**)&s_xn,   g_xn);
    cudaGetSymbolAddress((void**)&s_qkv,  g_qkv);
    cudaGetSymbolAddress((void**)&s_gate, g_gate);
    cudaGetSymbolAddress((void**)&s_y,    g_y);
    cudaGetSymbolAddress((void**)&s_x1,   g_x1);
    cudaGetSymbolAddress((void**)&s_xn2,  g_xn2);
    cudaGetSymbolAddress((void**)&s_h,    g_h);
    cudaGetSymbolAddress((void**)&s_wqkv, g_wqkv);
    cudaGetSymbolAddress((void**)&s_wgate,g_wgate);
    cudaGetSymbolAddress((void**)&s_wout, g_wout);
    cudaGetSymbolAddress((void**)&s_wfc1, g_wfc1);
    cudaGetSymbolAddress((void**)&s_wfc2, g_wfc2);

    const float* x      = (const float*)d_in[0];
    const float* ln1_g  = (const float*)d_in[1];
    const float* ln1_b  = (const float*)d_in[2];
    const float* qkv_w  = (const float*)d_in[3];
    const float* qkv_b  = (const float*)d_in[4];
    const float* gate_w = (const float*)d_in[5];
    const float* gate_b = (const float*)d_in[6];
    const float* out_w  = (const float*)d_in[7];
    const float* out_b  = (const float*)d_in[8];
    const float* pbias  = (const float*)d_in[9];
    const float* ln2_g  = (const float*)d_in[10];
    const float* ln2_b  = (const float*)d_in[11];
    const float* fc1_w  = (const float*)d_in[12];
    const float* fc1_b  = (const float*)d_in[13];
    const float* fc2_w  = (const float*)d_in[14];
    const float* fc2_b  = (const float*)d_in[15];
    float* out = (float*)d_out;

    // weight tf32 rounding
    cvt_kernel<<<(DMODEL * D3 / 4) / 256, 256>>>((const float4*)qkv_w, (float4*)s_wqkv, DMODEL * D3 / 4);
    cvt_kernel<<<(DMODEL * DMODEL / 4) / 256, 256>>>((const float4*)gate_w, (float4*)s_wgate, DMODEL * DMODEL / 4);
    cvt_kernel<<<(DMODEL * DMODEL / 4) / 256, 256>>>((const float4*)out_w, (float4*)s_wout, DMODEL * DMODEL / 4);
    cvt_kernel<<<(DMODEL * DFF / 4) / 256, 256>>>((const float4*)fc1_w, (float4*)s_wfc1, DMODEL * DFF / 4);
    cvt_kernel<<<(DFF * DMODEL / 4) / 256, 256>>>((const float4*)fc2_w, (float4*)s_wfc2, DFF * DMODEL / 4);

    // 1) LN1 (tf32-rounded output)
    ln_kernel<<<NSEQ, 256>>>(x, ln1_g, ln1_b, s_xn);
    // 2) qkv = xn @ qkv_w + qkv_b
    tgemm<128, 0, false><<<dim3(D3 / 128, NSEQ / 128), 256>>>(
        s_xn, s_wqkv, qkv_b, nullptr, s_qkv, D3, DMODEL);
    // 3) gate = sigmoid(xn @ gate_w + gate_b)
    tgemm<64, 1, false><<<dim3(DMODEL / 128, NSEQ / 64), 256>>>(
        s_xn, s_wgate, gate_b, nullptr, s_gate, DMODEL, DMODEL);
    // 4) attention (+gate, tf32-rounded)
    attn_kernel<<<(NSEQ * NHEAD * 32) / 256, 256>>>(s_qkv, s_gate, pbias, s_y);
    // 5) x1 = x + y @ out_w + out_b
    tgemm<64, 2, false><<<dim3(DMODEL / 128, NSEQ / 64), 256>>>(
        s_y, s_wout, out_b, x, s_x1, DMODEL, DMODEL);
    // 6) LN2 (tf32-rounded output)
    ln_kernel<<<NSEQ, 256>>>(s_x1, ln2_g, ln2_b, s_xn2);
    // 7) h = gelu(xn2 @ fc1_w + fc1_b), tf32-rounded
    tgemm<128, 3, true><<<dim3(DFF / 128, NSEQ / 128), 256>>>(
        s_xn2, s_wfc1, fc1_b, nullptr, s_h, DFF, DMODEL);
    // 8) out = x1 + h @ fc2_w + fc2_b
    tgemm<64, 2, false><<<dim3(DMODEL / 128, NSEQ / 64), 256>>>(
        s_h, s_wfc2, fc2_b, s_x1, out, DMODEL, DFF);
}

// round 3
// speedup vs baseline: 3.8210x; 1.4179x over previous
#include <cuda_runtime.h>
#include <cuda_bf16.h>
#include <math.h>
#include <stdint.h>

// ---------------------------------------------------------------------------
// Problem constants
// ---------------------------------------------------------------------------
#define NSEQ 2048
#define DMODEL 1024
#define NHEAD 16
#define HDIM 64
#define DFF 4096
#define NOFF 44
#define D3 (3 * DMODEL)

__constant__ int c_offs[NOFF] = {
    0,1,2,3,4,5,6,7,8,9,10,11,12,13,14,15,16,17,18,19,20,21,22,23,24,25,26,27,
    28,29,30,31,32,48,64,96,128,192,256,384,512,768,1024,1536};

// ---------------------------------------------------------------------------
// Scratch (__device__ globals; no allocation allowed)
// ---------------------------------------------------------------------------
__device__ float g_xn [NSEQ * DMODEL];
__device__ float g_qkv[NSEQ * D3];
__device__ float g_gate[NSEQ * DMODEL];
__device__ float g_y  [NSEQ * DMODEL];
__device__ float g_x1 [NSEQ * DMODEL];
__device__ float g_xn2[NSEQ * DMODEL];
__device__ float g_h  [NSEQ * DFF];
__device__ float g_wqkv [DMODEL * D3];
__device__ float g_wgate[DMODEL * DMODEL];
__device__ float g_wout [DMODEL * DMODEL];
__device__ float g_wfc1 [DMODEL * DFF];
__device__ float g_wfc2 [DFF * DMODEL];

// ---------------------------------------------------------------------------
__device__ __forceinline__ float f2tf(float x) {
    uint32_t u;
    asm("cvt.rna.tf32.f32 %0, %1;" : "=r"(u) : "f"(x));
    return __uint_as_float(u);
}

__global__ void cvt_kernel(const float4* __restrict__ in, float4* __restrict__ out, int n4) {
    int i = blockIdx.x * 256 + threadIdx.x;
    if (i < n4) {
        float4 v = in[i];
        v.x = f2tf(v.x); v.y = f2tf(v.y); v.z = f2tf(v.z); v.w = f2tf(v.w);
        out[i] = v;
    }
}

// ---------------------------------------------------------------------------
// LayerNorm (output tf32-rounded)
// ---------------------------------------------------------------------------
__global__ void ln_kernel(const float* __restrict__ x,
                          const float* __restrict__ g,
                          const float* __restrict__ b,
                          float* __restrict__ out) {
    int row = blockIdx.x;
    int tid = threadIdx.x;
    const float4* xr = (const float4*)(x + (size_t)row * DMODEL);
    float4 v = xr[tid];
    float s  = v.x + v.y + v.z + v.w;
    float sq = v.x * v.x + v.y * v.y + v.z * v.z + v.w * v.w;
    #pragma unroll
    for (int o = 16; o > 0; o >>= 1) {
        s  += __shfl_xor_sync(0xffffffffu, s,  o);
        sq += __shfl_xor_sync(0xffffffffu, sq, o);
    }
    __shared__ float sh[16];
    int wid = tid >> 5, lane = tid & 31;
    if (lane == 0) { sh[wid] = s; sh[wid + 8] = sq; }
    __syncthreads();
    float ts = 0.f, tq = 0.f;
    #pragma unroll
    for (int w = 0; w < 8; w++) { ts += sh[w]; tq += sh[w + 8]; }
    float mu  = ts * (1.0f / DMODEL);
    float var = tq * (1.0f / DMODEL) - mu * mu;
    var = var > 0.f ? var : 0.f;
    float rstd = rsqrtf(var + 1e-5f);

    float4 gv = ((const float4*)g)[tid];
    float4 bv = ((const float4*)b)[tid];
    float4 ov;
    ov.x = f2tf((v.x - mu) * rstd * gv.x + bv.x);
    ov.y = f2tf((v.y - mu) * rstd * gv.y + bv.y);
    ov.z = f2tf((v.z - mu) * rstd * gv.z + bv.z);
    ov.w = f2tf((v.w - mu) * rstd * gv.w + bv.w);
    ((float4*)(out + (size_t)row * DMODEL))[tid] = ov;
}

// ---------------------------------------------------------------------------
// tf32 tensor GEMM v2: BM x 128 x 32 tiles, 4 warps (2x2), warp tile (BM/2)x64
// double-buffered dynamic smem, mma.m16n8k8.
//   EPI 0: +bias | 1: sigmoid | 2: +bias+res | 3: gelu_exact ; CVT: tf32-round
// ---------------------------------------------------------------------------
#define CPA16(dst, src) \
    asm volatile("cp.async.cg.shared.global [%0], [%1], 16;\n" :: "r"(dst), "l"(src))

template <int BM, int EPI, bool CVT>
__global__ void __launch_bounds__(128)
tgemm(const float* __restrict__ A, const float* __restrict__ B,
      const float* __restrict__ bias, const float* __restrict__ res,
      float* __restrict__ C, int N, int K) {
    constexpr int BN = 128, BK = 32;
    constexpr int AS = BK + 4;    // 36
    constexpr int BS = BN + 8;    // 136
    constexpr int MI = BM / 32;   // m16 tiles per warp (warp covers BM/2 rows)
    constexpr int NI = 8;         // warp covers 64 cols
    constexpr int AIT = BM / 16;  // A cp.async iters per thread
    constexpr int ABUFF = BM * AS;  // floats per A stage
    constexpr int BBUFF = BK * BS;

    extern __shared__ float sm[];
    float* smA = sm;                    // [2][ABUFF]
    float* smB = sm + 2 * ABUFF;        // [2][BBUFF]

    const int tid  = threadIdx.x;
    const int warp = tid >> 5, lane = tid & 31;
    const int g    = lane >> 2, t4 = lane & 3;
    const int warpM = (warp >> 1) * (BM / 2);
    const int warpN = (warp & 1) * 64;
    const int rowBase = blockIdx.y * BM;
    const int colBase = blockIdx.x * BN;

    const int aRow0 = tid >> 3;           // 0..15
    const int aC    = (tid & 7) * 4;      // 0..28
    const int bRow0 = tid >> 5;           // 0..3
    const int bC    = (tid & 31) * 4;     // 0..124

    const uint32_t sa = (uint32_t)__cvta_generic_to_shared(smA);
    const uint32_t sb = (uint32_t)__cvta_generic_to_shared(smB);
    const uint32_t ABYTES = ABUFF * 4;
    const uint32_t BBYTES = BBUFF * 4;

    const float* Agp = A + (size_t)(rowBase + aRow0) * K + aC;
    const float* Bgp = B + (size_t)bRow0 * N + colBase + bC;

    float acc[MI][NI][4];
    #pragma unroll
    for (int mi = 0; mi < MI; mi++)
        #pragma unroll
        for (int ni = 0; ni < NI; ni++)
            #pragma unroll
            for (int r = 0; r < 4; r++) acc[mi][ni][r] = 0.f;

    const uint32_t daBase = sa + ((uint32_t)(aRow0 * AS + aC)) * 4;
    const uint32_t dbBase = sb + ((uint32_t)(bRow0 * BS + bC)) * 4;

    // prologue: tile 0 into buffer 0
    {
        #pragma unroll
        for (int i = 0; i < AIT; i++)
            CPA16(daBase + (uint32_t)(i * 16 * AS) * 4, Agp + (size_t)i * 16 * K);
        #pragma unroll
        for (int i = 0; i < 8; i++)
            CPA16(dbBase + (uint32_t)(i * 4 * BS) * 4, Bgp + (size_t)i * 4 * N);
        asm volatile("cp.async.commit_group;\n");
    }

    const int KT = K / BK;
    for (int kt = 0; kt < KT; kt++) {
        const int buf = kt & 1;
        if (kt + 1 < KT) {
            const int nb = buf ^ 1;
            const float* pa = Agp + (kt + 1) * BK;
            #pragma unroll
            for (int i = 0; i < AIT; i++)
                CPA16(daBase + nb * ABYTES + (uint32_t)(i * 16 * AS) * 4,
                      pa + (size_t)i * 16 * K);
            const float* pb = Bgp + (size_t)(kt + 1) * BK * N;
            #pragma unroll
            for (int i = 0; i < 8; i++)
                CPA16(dbBase + nb * BBYTES + (uint32_t)(i * 4 * BS) * 4,
                      pb + (size_t)i * 4 * N);
            asm volatile("cp.async.commit_group;\n");
            asm volatile("cp.async.wait_group 1;\n");
        } else {
            asm volatile("cp.async.wait_group 0;\n");
        }
        __syncthreads();

        const uint32_t* pA = (const uint32_t*)(smA + buf * ABUFF);
        const uint32_t* pB = (const uint32_t*)(smB + buf * BBUFF);
        #pragma unroll
        for (int ks = 0; ks < 4; ks++) {
            uint32_t af[MI][4], bf[NI][2];
            #pragma unroll
            for (int mi = 0; mi < MI; mi++) {
                int m = warpM + mi * 16 + g;
                af[mi][0] = pA[m * AS + ks * 8 + t4];
                af[mi][1] = pA[(m + 8) * AS + ks * 8 + t4];
                af[mi][2] = pA[m * AS + ks * 8 + t4 + 4];
                af[mi][3] = pA[(m + 8) * AS + ks * 8 + t4 + 4];
            }
            #pragma unroll
            for (int ni = 0; ni < NI; ni++) {
                int nn = warpN + ni * 8 + g;
                bf[ni][0] = pB[(ks * 8 + t4) * BS + nn];
                bf[ni][1] = pB[(ks * 8 + t4 + 4) * BS + nn];
            }
            #pragma unroll
            for (int mi = 0; mi < MI; mi++)
                #pragma unroll
                for (int ni = 0; ni < NI; ni++)
                    asm volatile(
                        "mma.sync.aligned.m16n8k8.row.col.f32.tf32.tf32.f32 "
                        "{%0,%1,%2,%3}, {%4,%5,%6,%7}, {%8,%9}, {%0,%1,%2,%3};\n"
                        : "+f"(acc[mi][ni][0]), "+f"(acc[mi][ni][1]),
                          "+f"(acc[mi][ni][2]), "+f"(acc[mi][ni][3])
                        : "r"(af[mi][0]), "r"(af[mi][1]), "r"(af[mi][2]), "r"(af[mi][3]),
                          "r"(bf[ni][0]), "r"(bf[ni][1]));
        }
        __syncthreads();
    }

    // epilogue
    #pragma unroll
    for (int mi = 0; mi < MI; mi++) {
        #pragma unroll
        for (int ni = 0; ni < NI; ni++) {
            int row = rowBase + warpM + mi * 16 + g;
            int col = colBase + warpN + ni * 8 + t4 * 2;
            float b0 = bias[col], b1 = bias[col + 1];
            #pragma unroll
            for (int half = 0; half < 2; half++) {
                int r = row + half * 8;
                float vx = acc[mi][ni][half * 2 + 0] + b0;
                float vy = acc[mi][ni][half * 2 + 1] + b1;
                if (EPI == 1) {
                    vx = 1.0f / (1.0f + expf(-vx));
                    vy = 1.0f / (1.0f + expf(-vy));
                } else if (EPI == 3) {
                    vx = 0.5f * vx * (1.0f + erff(vx * 0.70710678118654752f));
                    vy = 0.5f * vy * (1.0f + erff(vy * 0.70710678118654752f));
                }
                if (EPI == 2) {
                    float2 rr = *(const float2*)(res + (size_t)r * N + col);
                    vx += rr.x; vy += rr.y;
                }
                if (CVT) { vx = f2tf(vx); vy = f2tf(vy); }
                *(float2*)(C + (size_t)r * N + col) = make_float2(vx, vy);
            }
        }
    }
}

// ---------------------------------------------------------------------------
// Offset attention v2: one warp per (n,h); 4 offset-groups x 8 dim-lanes.
// Group g handles offsets {g, g+4, ..., g+40}; lane j owns dims 8j..8j+7.
// ---------------------------------------------------------------------------
__global__ void attn_kernel(const float* __restrict__ qkv,
                            const float* __restrict__ gate,
                            const float* __restrict__ pos_bias,
                            float* __restrict__ y) {
    int warp = (blockIdx.x * blockDim.x + threadIdx.x) >> 5;
    int lane = threadIdx.x & 31;
    int n = warp >> 4;
    int h = warp & 15;
    int j = lane & 7;     // dim octet
    int g = lane >> 3;    // offset group

    const float* qrow  = qkv + (size_t)n * D3 + h * HDIM + j * 8;
    const float* kbase = qkv + DMODEL + h * HDIM + j * 8;
    const float* vbase = qkv + 2 * DMODEL + h * HDIM + j * 8;

    float4 q0 = *(const float4*)(qrow);
    float4 q1 = *(const float4*)(qrow + 4);

    const float scale = 0.125f;
    float s[11];

    #pragma unroll
    for (int i = 0; i < 11; i++) {
        int o = i * 4 + g;
        int delta = c_offs[o];
        bool valid = (delta <= n);
        float p = 0.f;
        if (valid) {
            const float* kr = kbase + (size_t)(n - delta) * D3;
            float4 k0 = *(const float4*)(kr);
            float4 k1 = *(const float4*)(kr + 4);
            p = q0.x * k0.x + q0.y * k0.y + q0.z * k0.z + q0.w * k0.w
              + q1.x * k1.x + q1.y * k1.y + q1.z * k1.z + q1.w * k1.w;
        }
        p += __shfl_xor_sync(0xffffffffu, p, 1);
        p += __shfl_xor_sync(0xffffffffu, p, 2);
        p += __shfl_xor_sync(0xffffffffu, p, 4);
        s[i] = valid ? p * scale + pos_bias[o * NHEAD + h] : -INFINITY;
    }

    float mx = s[0];
    #pragma unroll
    for (int i = 1; i < 11; i++) mx = fmaxf(mx, s[i]);
    mx = fmaxf(mx, __shfl_xor_sync(0xffffffffu, mx, 8));
    mx = fmaxf(mx, __shfl_xor_sync(0xffffffffu, mx, 16));

    float denom = 0.f;
    #pragma unroll
    for (int i = 0; i < 11; i++) {
        s[i] = expf(s[i] - mx);      // -inf -> 0
        denom += s[i];
    }
    denom += __shfl_xor_sync(0xffffffffu, denom, 8);
    denom += __shfl_xor_sync(0xffffffffu, denom, 16);

    float acc[8] = {0.f, 0.f, 0.f, 0.f, 0.f, 0.f, 0.f, 0.f};
    #pragma unroll
    for (int i = 0; i < 11; i++) {
        int o = i * 4 + g;
        int delta = c_offs[o];
        if (delta <= n) {
            const float* vr = vbase + (size_t)(n - delta) * D3;
            float4 v0 = *(const float4*)(vr);
            float4 v1 = *(const float4*)(vr + 4);
            float w = s[i];
            acc[0] = fmaf(w, v0.x, acc[0]);
            acc[1] = fmaf(w, v0.y, acc[1]);
            acc[2] = fmaf(w, v0.z, acc[2]);
            acc[3] = fmaf(w, v0.w, acc[3]);
            acc[4] = fmaf(w, v1.x, acc[4]);
            acc[5] = fmaf(w, v1.y, acc[5]);
            acc[6] = fmaf(w, v1.z, acc[6]);
            acc[7] = fmaf(w, v1.w, acc[7]);
        }
    }
    #pragma unroll
    for (int d = 0; d < 8; d++) {
        acc[d] += __shfl_xor_sync(0xffffffffu, acc[d], 8);
        acc[d] += __shfl_xor_sync(0xffffffffu, acc[d], 16);
    }

    if (g == 0) {
        float inv = 1.0f / denom;
        size_t yoff = (size_t)n * DMODEL + h * HDIM + j * 8;
        float4 g0 = *(const float4*)(gate + yoff);
        float4 g1 = *(const float4*)(gate + yoff + 4);
        float4 o0, o1;
        o0.x = f2tf(acc[0] * inv * g0.x);
        o0.y = f2tf(acc[1] * inv * g0.y);
        o0.z = f2tf(acc[2] * inv * g0.z);
        o0.w = f2tf(acc[3] * inv * g0.w);
        o1.x = f2tf(acc[4] * inv * g1.x);
        o1.y = f2tf(acc[5] * inv * g1.y);
        o1.z = f2tf(acc[6] * inv * g1.z);
        o1.w = f2tf(acc[7] * inv * g1.w);
        *(float4*)(y + yoff)     = o0;
        *(float4*)(y + yoff + 4) = o1;
    }
}

// ---------------------------------------------------------------------------
// Launch
// ---------------------------------------------------------------------------
extern "C" void kernel_launch(void* const* d_in, const int* in_sizes, int n_in,
                              void* d_out, int out_size) {
    float *s_xn, *s_qkv, *s_gate, *s_y, *s_x1, *s_xn2, *s_h;
    float *s_wqkv, *s_wgate, *s_wout, *s_wfc1, *s_wfc2;
    cudaGetSymbolAddress((void**)&s_xn,   g_xn);
    cudaGetSymbolAddress((void**)&s_qkv,  g_qkv);
    cudaGetSymbolAddress((void**)&s_gate, g_gate);
    cudaGetSymbolAddress((void**)&s_y,    g_y);
    cudaGetSymbolAddress((void**)&s_x1,   g_x1);
    cudaGetSymbolAddress((void**)&s_xn2,  g_xn2);
    cudaGetSymbolAddress((void**)&s_h,    g_h);
    cudaGetSymbolAddress((void**)&s_wqkv, g_wqkv);
    cudaGetSymbolAddress((void**)&s_wgate,g_wgate);
    cudaGetSymbolAddress((void**)&s_wout, g_wout);
    cudaGetSymbolAddress((void**)&s_wfc1, g_wfc1);
    cudaGetSymbolAddress((void**)&s_wfc2, g_wfc2);

    const float* x      = (const float*)d_in[0];
    const float* ln1_g  = (const float*)d_in[1];
    const float* ln1_b  = (const float*)d_in[2];
    const float* qkv_w  = (const float*)d_in[3];
    const float* qkv_b  = (const float*)d_in[4];
    const float* gate_w = (const float*)d_in[5];
    const float* gate_b = (const float*)d_in[6];
    const float* out_w  = (const float*)d_in[7];
    const float* out_b  = (const float*)d_in[8];
    const float* pbias  = (const float*)d_in[9];
    const float* ln2_g  = (const float*)d_in[10];
    const float* ln2_b  = (const float*)d_in[11];
    const float* fc1_w  = (const float*)d_in[12];
    const float* fc1_b  = (const float*)d_in[13];
    const float* fc2_w  = (const float*)d_in[14];
    const float* fc2_b  = (const float*)d_in[15];
    float* out = (float*)d_out;

    // dynamic smem sizes
    const int SM128 = (2 * 128 * 36 + 2 * 32 * 136) * 4;  // 71680
    const int SM64  = (2 * 64  * 36 + 2 * 32 * 136) * 4;  // 53248
    cudaFuncSetAttribute(tgemm<128,0,false>, cudaFuncAttributeMaxDynamicSharedMemorySize, SM128);
    cudaFuncSetAttribute(tgemm<128,3,true >, cudaFuncAttributeMaxDynamicSharedMemorySize, SM128);
    cudaFuncSetAttribute(tgemm<64,1,false >, cudaFuncAttributeMaxDynamicSharedMemorySize, SM64);
    cudaFuncSetAttribute(tgemm<64,2,false >, cudaFuncAttributeMaxDynamicSharedMemorySize, SM64);

    // weight tf32 rounding
    cvt_kernel<<<(DMODEL * D3 / 4) / 256, 256>>>((const float4*)qkv_w, (float4*)s_wqkv, DMODEL * D3 / 4);
    cvt_kernel<<<(DMODEL * DMODEL / 4) / 256, 256>>>((const float4*)gate_w, (float4*)s_wgate, DMODEL * DMODEL / 4);
    cvt_kernel<<<(DMODEL * DMODEL / 4) / 256, 256>>>((const float4*)out_w, (float4*)s_wout, DMODEL * DMODEL / 4);
    cvt_kernel<<<(DMODEL * DFF / 4) / 256, 256>>>((const float4*)fc1_w, (float4*)s_wfc1, DMODEL * DFF / 4);
    cvt_kernel<<<(DFF * DMODEL / 4) / 256, 256>>>((const float4*)fc2_w, (float4*)s_wfc2, DFF * DMODEL / 4);

    // 1) LN1
    ln_kernel<<<NSEQ, 256>>>(x, ln1_g, ln1_b, s_xn);
    // 2) qkv
    tgemm<128,0,false><<<dim3(D3 / 128, NSEQ / 128), 128, SM128>>>(
        s_xn, s_wqkv, qkv_b, nullptr, s_qkv, D3, DMODEL);
    // 3) gate
    tgemm<64,1,false><<<dim3(DMODEL / 128, NSEQ / 64), 128, SM64>>>(
        s_xn, s_wgate, gate_b, nullptr, s_gate, DMODEL, DMODEL);
    // 4) attention
    attn_kernel<<<(NSEQ * NHEAD) / 8, 256>>>(s_qkv, s_gate, pbias, s_y);
    // 5) x1 = x + y @ out_w + out_b
    tgemm<64,2,false><<<dim3(DMODEL / 128, NSEQ / 64), 128, SM64>>>(
        s_y, s_wout, out_b, x, s_x1, DMODEL, DMODEL);
    // 6) LN2
    ln_kernel<<<NSEQ, 256>>>(s_x1, ln2_g, ln2_b, s_xn2);
    // 7) h = gelu(fc1)
    tgemm<128,3,true><<<dim3(DFF / 128, NSEQ / 128), 128, SM128>>>(
        s_xn2, s_wfc1, fc1_b, nullptr, s_h, DFF, DMODEL);
    // 8) out = x1 + h @ fc2_w + fc2_b
    tgemm<64,2,false><<<dim3(DMODEL / 128, NSEQ / 64), 128, SM64>>>(
        s_h, s_wfc2, fc2_b, s_x1, out, DMODEL, DFF);
}

// round 6
// speedup vs baseline: 5.9265x; 1.5511x over previous
#include <cuda_runtime.h>
#include <cuda_fp16.h>
#include <math.h>
#include <stdint.h>

// ---------------------------------------------------------------------------
// Problem constants
// ---------------------------------------------------------------------------
#define NSEQ 2048
#define DMODEL 1024
#define NHEAD 16
#define HDIM 64
#define DFF 4096
#define NOFF 44
#define D3 (3 * DMODEL)

__constant__ int c_offs[NOFF] = {
    0,1,2,3,4,5,6,7,8,9,10,11,12,13,14,15,16,17,18,19,20,21,22,23,24,25,26,27,
    28,29,30,31,32,48,64,96,128,192,256,384,512,768,1024,1536};

// ---------------------------------------------------------------------------
// Scratch (__device__ globals; no allocation allowed)
// ---------------------------------------------------------------------------
__device__ __half g_xn [NSEQ * DMODEL];   // LN1(x) fp16
__device__ __half g_qkv[NSEQ * D3];       // qkv fp16
__device__ __half g_gate[NSEQ * DMODEL];  // sigmoid gate fp16
__device__ __half g_y  [NSEQ * DMODEL];   // attn*gate fp16
__device__ float  g_x1 [NSEQ * DMODEL];   // x + attn_out fp32 (residual stream)
__device__ __half g_xn2[NSEQ * DMODEL];   // LN2(x1) fp16
__device__ __half g_h  [NSEQ * DFF];      // gelu(fc1) fp16
// transposed fp16 weights, [N, K] K-major
__device__ __half g_wqkv [D3 * DMODEL];
__device__ __half g_wgate[DMODEL * DMODEL];
__device__ __half g_wout [DMODEL * DMODEL];
__device__ __half g_wfc1 [DFF * DMODEL];
__device__ __half g_wfc2 [DMODEL * DFF];

// ---------------------------------------------------------------------------
// Helpers
// ---------------------------------------------------------------------------
__device__ __forceinline__ uint32_t smem_u32(const void* p) {
    uint32_t a;
    asm("{ .reg .u64 t; cvta.to.shared.u64 t, %1; cvt.u32.u64 %0, t; }"
        : "=r"(a) : "l"(p));
    return a;
}

#define CPA16(dst, src) \
    asm volatile("cp.async.cg.shared.global [%0], [%1], 16;\n" :: "r"(dst), "l"(src))

__device__ __forceinline__ float2 h2f2(uint32_t u) {
    __half2 h = *(__half2*)&u;
    return __half22float2(h);
}

// ---------------------------------------------------------------------------
// Weight prep: transpose [K,N] fp32 -> [N,K] fp16
// ---------------------------------------------------------------------------
__global__ void wprep(const float* __restrict__ W, __half* __restrict__ Wt,
                      int K, int N) {
    __shared__ float t[32][33];
    int n0 = blockIdx.x * 32, k0 = blockIdx.y * 32;
    int tx = threadIdx.x, ty = threadIdx.y;
    #pragma unroll
    for (int i = 0; i < 32; i += 8)
        t[ty + i][tx] = W[(size_t)(k0 + ty + i) * N + n0 + tx];
    __syncthreads();
    #pragma unroll
    for (int i = 0; i < 32; i += 8)
        Wt[(size_t)(n0 + ty + i) * K + k0 + tx] = __float2half_rn(t[tx][ty + i]);
}

// ---------------------------------------------------------------------------
// LayerNorm: one block/row, 256 threads, 4 floats/thread, fp16 output
// ---------------------------------------------------------------------------
__global__ void ln_kernel(const float* __restrict__ x,
                          const float* __restrict__ g,
                          const float* __restrict__ b,
                          __half* __restrict__ out) {
    int row = blockIdx.x;
    int tid = threadIdx.x;
    const float4* xr = (const float4*)(x + (size_t)row * DMODEL);
    float4 v = xr[tid];
    float s  = v.x + v.y + v.z + v.w;
    float sq = v.x * v.x + v.y * v.y + v.z * v.z + v.w * v.w;
    #pragma unroll
    for (int o = 16; o > 0; o >>= 1) {
        s  += __shfl_xor_sync(0xffffffffu, s,  o);
        sq += __shfl_xor_sync(0xffffffffu, sq, o);
    }
    __shared__ float sh[16];
    int wid = tid >> 5, lane = tid & 31;
    if (lane == 0) { sh[wid] = s; sh[wid + 8] = sq; }
    __syncthreads();
    float ts = 0.f, tq = 0.f;
    #pragma unroll
    for (int w = 0; w < 8; w++) { ts += sh[w]; tq += sh[w + 8]; }
    float mu  = ts * (1.0f / DMODEL);
    float var = tq * (1.0f / DMODEL) - mu * mu;
    var = var > 0.f ? var : 0.f;
    float rstd = rsqrtf(var + 1e-5f);

    float4 gv = ((const float4*)g)[tid];
    float4 bv = ((const float4*)b)[tid];
    __half2 h0 = __floats2half2_rn((v.x - mu) * rstd * gv.x + bv.x,
                                   (v.y - mu) * rstd * gv.y + bv.y);
    __half2 h1 = __floats2half2_rn((v.z - mu) * rstd * gv.z + bv.z,
                                   (v.w - mu) * rstd * gv.w + bv.w);
    uint2 o;
    o.x = *(uint32_t*)&h0;
    o.y = *(uint32_t*)&h1;
    *(uint2*)(out + (size_t)row * DMODEL + tid * 4) = o;
}

// ---------------------------------------------------------------------------
// fp16 tile loader: ROWS x 64 halves, row stride 144B (32 data words + 4 pad)
// ---------------------------------------------------------------------------
template <int ROWS, int NT>
__device__ __forceinline__ void tile_load(uint32_t dst, const __half* src,
                                          int ldK, int tid) {
    #pragma unroll
    for (int i = 0; i < ROWS * 8 / NT; i++) {
        int c = i * NT + tid;
        int m = c >> 3, q = c & 7;
        CPA16(dst + (uint32_t)(m * 144 + q * 16), src + (size_t)m * ldK + q * 8);
    }
}

// ---------------------------------------------------------------------------
// fp16 tensor GEMM: C[M,N] = A[M,K] @ Bt[N,K]^T (+bias, EPI epilogue)
// BM=128, BK=64(half), BN in {128,256}. Warp tile 64x64, mma.m16n8k16.f16.
//   EPI 0: +bias | 1: sigmoid | 2: +bias+res(fp32) | 3: gelu_exact
//   OUTH: write __half, else float
// ---------------------------------------------------------------------------
template <int BN, int EPI, bool OUTH>
__global__ void __launch_bounds__((128 / 64) * (BN / 64) * 32)
hgemm(const __half* __restrict__ A, const __half* __restrict__ Bt,
      const float* __restrict__ bias, const float* __restrict__ res,
      void* __restrict__ Cv, int N, int K) {
    constexpr int BM = 128;
    constexpr int WN = BN / 64;
    constexpr int NT = 2 * WN * 32;
    constexpr int MI = 4, NI = 8;
    constexpr uint32_t ASTAGE = BM * 144;   // bytes
    constexpr uint32_t BSTAGE = BN * 144;

    extern __shared__ char dsm[];

    const int tid  = threadIdx.x;
    const int warp = tid >> 5, lane = tid & 31;
    const int g    = lane >> 2, t4 = lane & 3;
    const int warpM = (warp / WN) * 64;
    const int warpN = (warp % WN) * 64;
    const int rowBase = blockIdx.y * BM;
    const int colBase = blockIdx.x * BN;

    const uint32_t sbase = smem_u32(dsm);
    const uint32_t smA = sbase;
    const uint32_t smB = sbase + 2 * ASTAGE;

    const __half* Ag = A + (size_t)rowBase * K;
    const __half* Bg = Bt + (size_t)colBase * K;

    float acc[MI][NI][4];
    #pragma unroll
    for (int mi = 0; mi < MI; mi++)
        #pragma unroll
        for (int ni = 0; ni < NI; ni++)
            #pragma unroll
            for (int r = 0; r < 4; r++) acc[mi][ni][r] = 0.f;

    // prologue: tile 0 -> buffer 0
    tile_load<BM, NT>(smA, Ag, K, tid);
    tile_load<BN, NT>(smB, Bg, K, tid);
    asm volatile("cp.async.commit_group;\n");

    const int KT = K / 64;
    for (int kt = 0; kt < KT; kt++) {
        const int buf = kt & 1;
        if (kt + 1 < KT) {
            const int nb = buf ^ 1;
            tile_load<BM, NT>(smA + nb * ASTAGE, Ag + (kt + 1) * 64, K, tid);
            tile_load<BN, NT>(smB + nb * BSTAGE, Bg + (kt + 1) * 64, K, tid);
            asm volatile("cp.async.commit_group;\n");
            asm volatile("cp.async.wait_group 1;\n");
        } else {
            asm volatile("cp.async.wait_group 0;\n");
        }
        __syncthreads();

        const uint32_t* wA = (const uint32_t*)(dsm + buf * ASTAGE);
        const uint32_t* wB = (const uint32_t*)(dsm + 2 * ASTAGE + buf * BSTAGE);
        #pragma unroll
        for (int ks = 0; ks < 4; ks++) {
            uint32_t af[MI][4], bf[NI][2];
            #pragma unroll
            for (int mi = 0; mi < MI; mi++) {
                int m = warpM + mi * 16 + g;
                af[mi][0] = wA[m * 36 + ks * 8 + t4];
                af[mi][1] = wA[(m + 8) * 36 + ks * 8 + t4];
                af[mi][2] = wA[m * 36 + ks * 8 + t4 + 4];
                af[mi][3] = wA[(m + 8) * 36 + ks * 8 + t4 + 4];
            }
            #pragma unroll
            for (int ni = 0; ni < NI; ni++) {
                int nn = warpN + ni * 8 + g;
                bf[ni][0] = wB[nn * 36 + ks * 8 + t4];
                bf[ni][1] = wB[nn * 36 + ks * 8 + t4 + 4];
            }
            #pragma unroll
            for (int mi = 0; mi < MI; mi++)
                #pragma unroll
                for (int ni = 0; ni < NI; ni++)
                    asm volatile(
                        "mma.sync.aligned.m16n8k16.row.col.f32.f16.f16.f32 "
                        "{%0,%1,%2,%3}, {%4,%5,%6,%7}, {%8,%9}, {%0,%1,%2,%3};\n"
                        : "+f"(acc[mi][ni][0]), "+f"(acc[mi][ni][1]),
                          "+f"(acc[mi][ni][2]), "+f"(acc[mi][ni][3])
                        : "r"(af[mi][0]), "r"(af[mi][1]), "r"(af[mi][2]), "r"(af[mi][3]),
                          "r"(bf[ni][0]), "r"(bf[ni][1]));
        }
        __syncthreads();
    }

    // epilogue
    #pragma unroll
    for (int mi = 0; mi < MI; mi++) {
        #pragma unroll
        for (int ni = 0; ni < NI; ni++) {
            int row = rowBase + warpM + mi * 16 + g;
            int col = colBase + warpN + ni * 8 + t4 * 2;
            float b0 = bias[col], b1 = bias[col + 1];
            #pragma unroll
            for (int half = 0; half < 2; half++) {
                int r = row + half * 8;
                float vx = acc[mi][ni][half * 2 + 0] + b0;
                float vy = acc[mi][ni][half * 2 + 1] + b1;
                if (EPI == 1) {
                    vx = 1.0f / (1.0f + expf(-vx));
                    vy = 1.0f / (1.0f + expf(-vy));
                } else if (EPI == 3) {
                    vx = 0.5f * vx * (1.0f + erff(vx * 0.70710678118654752f));
                    vy = 0.5f * vy * (1.0f + erff(vy * 0.70710678118654752f));
                }
                size_t off = (size_t)r * N + col;
                if (EPI == 2) {
                    float2 rr = *(const float2*)(res + off);
                    vx += rr.x; vy += rr.y;
                }
                if (OUTH) {
                    __half2 hv = __floats2half2_rn(vx, vy);
                    *(__half2*)((__half*)Cv + off) = hv;
                } else {
                    *(float2*)((float*)Cv + off) = make_float2(vx, vy);
                }
            }
        }
    }
}

// ---------------------------------------------------------------------------
// Offset attention (fp16 qkv/gate/y): one warp per (n,h);
// 4 offset-groups x 8 dim-lanes; lane j owns dims 8j..8j+7.
// ---------------------------------------------------------------------------
__global__ void attn_kernel(const __half* __restrict__ qkv,
                            const __half* __restrict__ gate,
                            const float* __restrict__ pos_bias,
                            __half* __restrict__ y) {
    int warp = (blockIdx.x * blockDim.x + threadIdx.x) >> 5;
    int lane = threadIdx.x & 31;
    int n = warp >> 4;
    int h = warp & 15;
    int j = lane & 7;
    int g = lane >> 3;

    const __half* qrow  = qkv + (size_t)n * D3 + h * HDIM + j * 8;
    const __half* kbase = qkv + DMODEL + h * HDIM + j * 8;
    const __half* vbase = qkv + 2 * DMODEL + h * HDIM + j * 8;

    uint4 qv = *(const uint4*)(qrow);
    float2 q0 = h2f2(qv.x), q1 = h2f2(qv.y), q2 = h2f2(qv.z), q3 = h2f2(qv.w);

    const float scale = 0.125f;
    float s[11];

    #pragma unroll
    for (int i = 0; i < 11; i++) {
        int o = i * 4 + g;
        int delta = c_offs[o];
        bool valid = (delta <= n);
        float p = 0.f;
        if (valid) {
            uint4 kv = *(const uint4*)(kbase + (size_t)(n - delta) * D3);
            float2 k0 = h2f2(kv.x), k1 = h2f2(kv.y), k2 = h2f2(kv.z), k3 = h2f2(kv.w);
            p = q0.x * k0.x + q0.y * k0.y + q1.x * k1.x + q1.y * k1.y
              + q2.x * k2.x + q2.y * k2.y + q3.x * k3.x + q3.y * k3.y;
        }
        p += __shfl_xor_sync(0xffffffffu, p, 1);
        p += __shfl_xor_sync(0xffffffffu, p, 2);
        p += __shfl_xor_sync(0xffffffffu, p, 4);
        s[i] = valid ? p * scale + pos_bias[o * NHEAD + h] : -INFINITY;
    }

    float mx = s[0];
    #pragma unroll
    for (int i = 1; i < 11; i++) mx = fmaxf(mx, s[i]);
    mx = fmaxf(mx, __shfl_xor_sync(0xffffffffu, mx, 8));
    mx = fmaxf(mx, __shfl_xor_sync(0xffffffffu, mx, 16));

    float denom = 0.f;
    #pragma unroll
    for (int i = 0; i < 11; i++) {
        s[i] = expf(s[i] - mx);
        denom += s[i];
    }
    denom += __shfl_xor_sync(0xffffffffu, denom, 8);
    denom += __shfl_xor_sync(0xffffffffu, denom, 16);

    float acc[8] = {0.f, 0.f, 0.f, 0.f, 0.f, 0.f, 0.f, 0.f};
    #pragma unroll
    for (int i = 0; i < 11; i++) {
        int o = i * 4 + g;
        int delta = c_offs[o];
        if (delta <= n) {
            uint4 vv = *(const uint4*)(vbase + (size_t)(n - delta) * D3);
            float2 v0 = h2f2(vv.x), v1 = h2f2(vv.y), v2 = h2f2(vv.z), v3 = h2f2(vv.w);
            float w = s[i];
            acc[0] = fmaf(w, v0.x, acc[0]);
            acc[1] = fmaf(w, v0.y, acc[1]);
            acc[2] = fmaf(w, v1.x, acc[2]);
            acc[3] = fmaf(w, v1.y, acc[3]);
            acc[4] = fmaf(w, v2.x, acc[4]);
            acc[5] = fmaf(w, v2.y, acc[5]);
            acc[6] = fmaf(w, v3.x, acc[6]);
            acc[7] = fmaf(w, v3.y, acc[7]);
        }
    }
    #pragma unroll
    for (int d = 0; d < 8; d++) {
        acc[d] += __shfl_xor_sync(0xffffffffu, acc[d], 8);
        acc[d] += __shfl_xor_sync(0xffffffffu, acc[d], 16);
    }

    if (g == 0) {
        float inv = 1.0f / denom;
        size_t yoff = (size_t)n * DMODEL + h * HDIM + j * 8;
        uint4 gv = *(const uint4*)(gate + yoff);
        float2 g0 = h2f2(gv.x), g1 = h2f2(gv.y), g2 = h2f2(gv.z), g3 = h2f2(gv.w);
        __half2 o0 = __floats2half2_rn(acc[0] * inv * g0.x, acc[1] * inv * g0.y);
        __half2 o1 = __floats2half2_rn(acc[2] * inv * g1.x, acc[3] * inv * g1.y);
        __half2 o2 = __floats2half2_rn(acc[4] * inv * g2.x, acc[5] * inv * g2.y);
        __half2 o3 = __floats2half2_rn(acc[6] * inv * g3.x, acc[7] * inv * g3.y);
        uint4 ov;
        ov.x = *(uint32_t*)&o0; ov.y = *(uint32_t*)&o1;
        ov.z = *(uint32_t*)&o2; ov.w = *(uint32_t*)&o3;
        *(uint4*)(y + yoff) = ov;
    }
}

// ---------------------------------------------------------------------------
// Launch
// ---------------------------------------------------------------------------
extern "C" void kernel_launch(void* const* d_in, const int* in_sizes, int n_in,
                              void* d_out, int out_size) {
    __half *s_xn, *s_qkv, *s_gate, *s_y, *s_xn2, *s_h;
    float *s_x1;
    __half *s_wqkv, *s_wgate, *s_wout, *s_wfc1, *s_wfc2;
    cudaGetSymbolAddress((void**)&s_xn,   g_xn);
    cudaGetSymbolAddress((void**)&s_qkv,  g_qkv);
    cudaGetSymbolAddress((void**)&s_gate, g_gate);
    cudaGetSymbolAddress((void**)&s_y,    g_y);
    cudaGetSymbolAddress((void**)&s_x1,   g_x1);
    cudaGetSymbolAddress((void**)&s_xn2,  g_xn2);
    cudaGetSymbolAddress((void**)&s_h,    g_h);
    cudaGetSymbolAddress((void**)&s_wqkv, g_wqkv);
    cudaGetSymbolAddress((void**)&s_wgate,g_wgate);
    cudaGetSymbolAddress((void**)&s_wout, g_wout);
    cudaGetSymbolAddress((void**)&s_wfc1, g_wfc1);
    cudaGetSymbolAddress((void**)&s_wfc2, g_wfc2);

    const float* x      = (const float*)d_in[0];
    const float* ln1_g  = (const float*)d_in[1];
    const float* ln1_b  = (const float*)d_in[2];
    const float* qkv_w  = (const float*)d_in[3];
    const float* qkv_b  = (const float*)d_in[4];
    const float* gate_w = (const float*)d_in[5];
    const float* gate_b = (const float*)d_in[6];
    const float* out_w  = (const float*)d_in[7];
    const float* out_b  = (const float*)d_in[8];
    const float* pbias  = (const float*)d_in[9];
    const float* ln2_g  = (const float*)d_in[10];
    const float* ln2_b  = (const float*)d_in[11];
    const float* fc1_w  = (const float*)d_in[12];
    const float* fc1_b  = (const float*)d_in[13];
    const float* fc2_w  = (const float*)d_in[14];
    const float* fc2_b  = (const float*)d_in[15];
    float* out = (float*)d_out;

    // dynamic smem: double-buffered A(128x144B) + B(BN x 144B)
    const int SM_BN128 = 2 * (128 * 144) + 2 * (128 * 144);  //  73728
    const int SM_BN256 = 2 * (128 * 144) + 2 * (256 * 144);  // 110592
    cudaFuncSetAttribute(hgemm<256,0,true >, cudaFuncAttributeMaxDynamicSharedMemorySize, SM_BN256);
    cudaFuncSetAttribute(hgemm<256,3,true >, cudaFuncAttributeMaxDynamicSharedMemorySize, SM_BN256);
    cudaFuncSetAttribute(hgemm<128,1,true >, cudaFuncAttributeMaxDynamicSharedMemorySize, SM_BN128);
    cudaFuncSetAttribute(hgemm<128,2,false>, cudaFuncAttributeMaxDynamicSharedMemorySize, SM_BN128);

    dim3 tb(32, 8);
    // weight transpose + fp16: W[K,N] -> Wt[N,K]
    wprep<<<dim3(D3 / 32,     DMODEL / 32), tb>>>(qkv_w,  s_wqkv,  DMODEL, D3);
    wprep<<<dim3(DMODEL / 32, DMODEL / 32), tb>>>(gate_w, s_wgate, DMODEL, DMODEL);
    wprep<<<dim3(DMODEL / 32, DMODEL / 32), tb>>>(out_w,  s_wout,  DMODEL, DMODEL);
    wprep<<<dim3(DFF / 32,    DMODEL / 32), tb>>>(fc1_w,  s_wfc1,  DMODEL, DFF);
    wprep<<<dim3(DMODEL / 32, DFF / 32),    tb>>>(fc2_w,  s_wfc2,  DFF, DMODEL);

    // 1) LN1 -> fp16
    ln_kernel<<<NSEQ, 256>>>(x, ln1_g, ln1_b, s_xn);
    // 2) qkv = xn @ qkv_w + qkv_b  (fp16 out)
    hgemm<256,0,true><<<dim3(D3 / 256, NSEQ / 128), 256, SM_BN256>>>(
        s_xn, s_wqkv, qkv_b, nullptr, s_qkv, D3, DMODEL);
    // 3) gate = sigmoid(xn @ gate_w + gate_b)  (fp16 out)
    hgemm<128,1,true><<<dim3(DMODEL / 128, NSEQ / 128), 128, SM_BN128>>>(
        s_xn, s_wgate, gate_b, nullptr, s_gate, DMODEL, DMODEL);
    // 4) attention (+gate)  (fp16 out)
    attn_kernel<<<(NSEQ * NHEAD) / 8, 256>>>(s_qkv, s_gate, pbias, s_y);
    // 5) x1 = x + y @ out_w + out_b  (fp32 out)
    hgemm<128,2,false><<<dim3(DMODEL / 128, NSEQ / 128), 128, SM_BN128>>>(
        s_y, s_wout, out_b, x, s_x1, DMODEL, DMODEL);
    // 6) LN2 -> fp16
    ln_kernel<<<NSEQ, 256>>>(s_x1, ln2_g, ln2_b, s_xn2);
    // 7) h = gelu(xn2 @ fc1_w + fc1_b)  (fp16 out)
    hgemm<256,3,true><<<dim3(DFF / 256, NSEQ / 128), 256, SM_BN256>>>(
        s_xn2, s_wfc1, fc1_b, nullptr, s_h, DFF, DMODEL);
    // 8) out = x1 + h @ fc2_w + fc2_b  (fp32 out)
    hgemm<128,2,false><<<dim3(DMODEL / 128, NSEQ / 128), 128, SM_BN128>>>(
        s_h, s_wfc2, fc2_b, s_x1, out, DMODEL, DFF);
}

// round 7
// speedup vs baseline: 6.0032x; 1.0129x over previous
#include <cuda_runtime.h>
#include <cuda_fp16.h>
#include <math.h>
#include <stdint.h>

// ---------------------------------------------------------------------------
#define NSEQ 2048
#define DMODEL 1024
#define NHEAD 16
#define HDIM 64
#define DFF 4096
#define NOFF 44
#define D3 (3 * DMODEL)
#define DQG 4096          // qkv + gate combined width

__constant__ int c_offs[NOFF] = {
    0,1,2,3,4,5,6,7,8,9,10,11,12,13,14,15,16,17,18,19,20,21,22,23,24,25,26,27,
    28,29,30,31,32,48,64,96,128,192,256,384,512,768,1024,1536};

// ---------------------------------------------------------------------------
// Scratch
// ---------------------------------------------------------------------------
__device__ __half g_xn [NSEQ * DMODEL];   // LN1(x) fp16
__device__ __half g_qg [NSEQ * DQG];      // [q|k|v|gate] fp16
__device__ __half g_y  [NSEQ * DMODEL];   // attn*gate fp16
__device__ float  g_x1 [NSEQ * DMODEL];   // residual fp32
__device__ __half g_xn2[NSEQ * DMODEL];   // LN2 fp16
__device__ __half g_h  [NSEQ * DFF];      // gelu(fc1) fp16
// transposed fp16 weights, [N,K] K-major
__device__ __half g_wqg [DQG * DMODEL];   // qkv rows 0-3071, gate rows 3072-4095
__device__ __half g_wout[DMODEL * DMODEL];
__device__ __half g_wfc1[DFF * DMODEL];
__device__ __half g_wfc2[DMODEL * DFF];
__device__ float  g_bqg [DQG];            // qkv_b | gate_b

// ---------------------------------------------------------------------------
__device__ __forceinline__ uint32_t smem_u32(const void* p) {
    uint32_t a;
    asm("{ .reg .u64 t; cvta.to.shared.u64 t, %1; cvt.u32.u64 %0, t; }"
        : "=r"(a) : "l"(p));
    return a;
}

#define CPA16(dst, src) \
    asm volatile("cp.async.cg.shared.global [%0], [%1], 16;\n" :: "r"(dst), "l"(src))

#define LDSM_X4(r0, r1, r2, r3, addr) \
    asm volatile("ldmatrix.sync.aligned.m8n8.x4.shared.b16 {%0,%1,%2,%3}, [%4];" \
        : "=r"(r0), "=r"(r1), "=r"(r2), "=r"(r3) : "r"(addr))

__device__ __forceinline__ float2 h2f2(uint32_t u) {
    __half2 h = *(__half2*)&u;
    return __half22float2(h);
}

// ---------------------------------------------------------------------------
// Fused weight prep: all transposes [K,N]fp32 -> [N,K]fp16 in one kernel
// ---------------------------------------------------------------------------
__global__ void prep_kernel(const float* __restrict__ qkv_w,
                            const float* __restrict__ gate_w,
                            const float* __restrict__ out_w,
                            const float* __restrict__ fc1_w,
                            const float* __restrict__ fc2_w) {
    __shared__ float t[32][33];
    int bid = blockIdx.x;
    const float* W; __half* Wt; int K, Nw, b;
    if (bid < 3072)       { b = bid;        W = qkv_w;  Wt = g_wqg;                       K = 1024; Nw = 3072; }
    else if (bid < 4096)  { b = bid - 3072; W = gate_w; Wt = g_wqg + (size_t)3072 * 1024; K = 1024; Nw = 1024; }
    else if (bid < 5120)  { b = bid - 4096; W = out_w;  Wt = g_wout;                      K = 1024; Nw = 1024; }
    else if (bid < 9216)  { b = bid - 5120; W = fc1_w;  Wt = g_wfc1;                      K = 1024; Nw = 4096; }
    else                  { b = bid - 9216; W = fc2_w;  Wt = g_wfc2;                      K = 4096; Nw = 1024; }
    int nx = Nw >> 5;
    int n0 = (b % nx) * 32, k0 = (b / nx) * 32;
    int tx = threadIdx.x, ty = threadIdx.y;
    #pragma unroll
    for (int i = 0; i < 32; i += 8)
        t[ty + i][tx] = W[(size_t)(k0 + ty + i) * Nw + n0 + tx];
    __syncthreads();
    #pragma unroll
    for (int i = 0; i < 32; i += 8)
        Wt[(size_t)(n0 + ty + i) * K + k0 + tx] = __float2half_rn(t[tx][ty + i]);
}

__global__ void bias_cat(const float* __restrict__ qkv_b,
                         const float* __restrict__ gate_b) {
    int i = blockIdx.x * 256 + threadIdx.x;
    if (i < DQG) g_bqg[i] = (i < D3) ? qkv_b[i] : gate_b[i - D3];
}

// ---------------------------------------------------------------------------
// LayerNorm -> fp16
// ---------------------------------------------------------------------------
__global__ void ln_kernel(const float* __restrict__ x,
                          const float* __restrict__ g,
                          const float* __restrict__ b,
                          __half* __restrict__ out) {
    int row = blockIdx.x;
    int tid = threadIdx.x;
    const float4* xr = (const float4*)(x + (size_t)row * DMODEL);
    float4 v = xr[tid];
    float s  = v.x + v.y + v.z + v.w;
    float sq = v.x * v.x + v.y * v.y + v.z * v.z + v.w * v.w;
    #pragma unroll
    for (int o = 16; o > 0; o >>= 1) {
        s  += __shfl_xor_sync(0xffffffffu, s,  o);
        sq += __shfl_xor_sync(0xffffffffu, sq, o);
    }
    __shared__ float sh[16];
    int wid = tid >> 5, lane = tid & 31;
    if (lane == 0) { sh[wid] = s; sh[wid + 8] = sq; }
    __syncthreads();
    float ts = 0.f, tq = 0.f;
    #pragma unroll
    for (int w = 0; w < 8; w++) { ts += sh[w]; tq += sh[w + 8]; }
    float mu  = ts * (1.0f / DMODEL);
    float var = tq * (1.0f / DMODEL) - mu * mu;
    var = var > 0.f ? var : 0.f;
    float rstd = rsqrtf(var + 1e-5f);

    float4 gv = ((const float4*)g)[tid];
    float4 bv = ((const float4*)b)[tid];
    __half2 h0 = __floats2half2_rn((v.x - mu) * rstd * gv.x + bv.x,
                                   (v.y - mu) * rstd * gv.y + bv.y);
    __half2 h1 = __floats2half2_rn((v.z - mu) * rstd * gv.z + bv.z,
                                   (v.w - mu) * rstd * gv.w + bv.w);
    uint2 o;
    o.x = *(uint32_t*)&h0;
    o.y = *(uint32_t*)&h1;
    *(uint2*)(out + (size_t)row * DMODEL + tid * 4) = o;
}

// ---------------------------------------------------------------------------
// fp16 tile loader: ROWS x 64 halves, row stride 144B
// ---------------------------------------------------------------------------
template <int ROWS, int NT>
__device__ __forceinline__ void tile_load(uint32_t dst, const __half* src,
                                          int ldK, int tid) {
    #pragma unroll
    for (int i = 0; i < ROWS * 8 / NT; i++) {
        int c = i * NT + tid;
        int m = c >> 3, q = c & 7;
        CPA16(dst + (uint32_t)(m * 144 + q * 16), src + (size_t)m * ldK + q * 8);
    }
}

// ---------------------------------------------------------------------------
// fp16 GEMM with ldmatrix + 3-stage cp.async pipeline.
// C[M,N] = A[M,K] @ Bt[N,K]^T, epilogue EPI:
//   2: +bias+res(fp32)->fp32 | 3: gelu->fp16 | 4: qkv|gate mixed ->fp16
// ---------------------------------------------------------------------------
template <int BM, int BN, int WM, int WN, int EPI, bool OUTH>
__global__ void __launch_bounds__(WM * WN * 32)
hgemm(const __half* __restrict__ A, const __half* __restrict__ Bt,
      const float* __restrict__ bias, const float* __restrict__ res,
      void* __restrict__ Cv, int N, int K) {
    constexpr int NT = WM * WN * 32;
    constexpr int MI = BM / WM / 16;
    constexpr int NI = BN / WN / 8;
    constexpr int NJ = NI / 2;
    constexpr uint32_t ASTAGE = BM * 144;
    constexpr uint32_t BSTAGE = BN * 144;

    extern __shared__ char dsm[];

    const int tid  = threadIdx.x;
    const int warp = tid >> 5, lane = tid & 31;
    const int g    = lane >> 2, t4 = lane & 3;
    const int warpM = (warp / WN) * (BM / WM);
    const int warpN = (warp % WN) * (BN / WN);
    const int rowBase = blockIdx.y * BM;
    const int colBase = blockIdx.x * BN;

    const uint32_t smA = smem_u32(dsm);
    const uint32_t smB = smA + 3 * ASTAGE;
    // ldmatrix per-lane base addresses (lane&15 -> row, lane>>4 -> 16B col half)
    const uint32_t aLds = smA + (uint32_t)((warpM + (lane & 15)) * 144 + (lane >> 4) * 16);
    const uint32_t bLds = smB + (uint32_t)((warpN + (lane & 15)) * 144 + (lane >> 4) * 16);

    const __half* Ag = A + (size_t)rowBase * K;
    const __half* Bg = Bt + (size_t)colBase * K;

    float acc[MI][NI][4];
    #pragma unroll
    for (int mi = 0; mi < MI; mi++)
        #pragma unroll
        for (int ni = 0; ni < NI; ni++)
            #pragma unroll
            for (int r = 0; r < 4; r++) acc[mi][ni][r] = 0.f;

    const int KT = K / 64;
    // prologue: stages 0, 1
    tile_load<BM, NT>(smA, Ag, K, tid);
    tile_load<BN, NT>(smB, Bg, K, tid);
    asm volatile("cp.async.commit_group;\n");
    if (KT > 1) {
        tile_load<BM, NT>(smA + ASTAGE, Ag + 64, K, tid);
        tile_load<BN, NT>(smB + BSTAGE, Bg + 64, K, tid);
        asm volatile("cp.async.commit_group;\n");
    }

    for (int kt = 0; kt < KT; kt++) {
        if (kt + 1 < KT) asm volatile("cp.async.wait_group 1;\n");
        else             asm volatile("cp.async.wait_group 0;\n");
        __syncthreads();

        // prefetch stage kt+2 before compute
        if (kt + 2 < KT) {
            const uint32_t nb = (uint32_t)((kt + 2) % 3);
            tile_load<BM, NT>(smA + nb * ASTAGE, Ag + (kt + 2) * 64, K, tid);
            tile_load<BN, NT>(smB + nb * BSTAGE, Bg + (kt + 2) * 64, K, tid);
            asm volatile("cp.async.commit_group;\n");
        }

        const uint32_t aOff = aLds + (uint32_t)(kt % 3) * ASTAGE;
        const uint32_t bOff = bLds + (uint32_t)(kt % 3) * BSTAGE;
        #pragma unroll
        for (int ks = 0; ks < 4; ks++) {
            uint32_t af[MI][4], bf[NJ][4];
            #pragma unroll
            for (int mi = 0; mi < MI; mi++)
                LDSM_X4(af[mi][0], af[mi][1], af[mi][2], af[mi][3],
                        aOff + (uint32_t)(mi * 16 * 144 + ks * 32));
            #pragma unroll
            for (int nj = 0; nj < NJ; nj++)
                LDSM_X4(bf[nj][0], bf[nj][1], bf[nj][2], bf[nj][3],
                        bOff + (uint32_t)(nj * 16 * 144 + ks * 32));
            #pragma unroll
            for (int mi = 0; mi < MI; mi++)
                #pragma unroll
                for (int nj = 0; nj < NJ; nj++) {
                    asm volatile(
                        "mma.sync.aligned.m16n8k16.row.col.f32.f16.f16.f32 "
                        "{%0,%1,%2,%3}, {%4,%5,%6,%7}, {%8,%9}, {%0,%1,%2,%3};\n"
                        : "+f"(acc[mi][2*nj][0]), "+f"(acc[mi][2*nj][1]),
                          "+f"(acc[mi][2*nj][2]), "+f"(acc[mi][2*nj][3])
                        : "r"(af[mi][0]), "r"(af[mi][1]), "r"(af[mi][2]), "r"(af[mi][3]),
                          "r"(bf[nj][0]), "r"(bf[nj][2]));
                    asm volatile(
                        "mma.sync.aligned.m16n8k16.row.col.f32.f16.f16.f32 "
                        "{%0,%1,%2,%3}, {%4,%5,%6,%7}, {%8,%9}, {%0,%1,%2,%3};\n"
                        : "+f"(acc[mi][2*nj+1][0]), "+f"(acc[mi][2*nj+1][1]),
                          "+f"(acc[mi][2*nj+1][2]), "+f"(acc[mi][2*nj+1][3])
                        : "r"(af[mi][0]), "r"(af[mi][1]), "r"(af[mi][2]), "r"(af[mi][3]),
                          "r"(bf[nj][1]), "r"(bf[nj][3]));
                }
        }
        __syncthreads();
    }

    // epilogue
    const bool sig = (EPI == 4) && (colBase >= D3);
    #pragma unroll
    for (int mi = 0; mi < MI; mi++) {
        #pragma unroll
        for (int ni = 0; ni < NI; ni++) {
            int row = rowBase + warpM + mi * 16 + g;
            int col = colBase + warpN + ni * 8 + t4 * 2;
            float b0 = bias[col], b1 = bias[col + 1];
            #pragma unroll
            for (int hh = 0; hh < 2; hh++) {
                int r = row + hh * 8;
                float vx = acc[mi][ni][hh * 2 + 0] + b0;
                float vy = acc[mi][ni][hh * 2 + 1] + b1;
                if (EPI == 3) {
                    vx = 0.5f * vx * (1.0f + erff(vx * 0.70710678118654752f));
                    vy = 0.5f * vy * (1.0f + erff(vy * 0.70710678118654752f));
                } else if (EPI == 4) {
                    if (sig) {
                        vx = 1.0f / (1.0f + __expf(-vx));
                        vy = 1.0f / (1.0f + __expf(-vy));
                    }
                }
                size_t off = (size_t)r * N + col;
                if (EPI == 2) {
                    float2 rr = *(const float2*)(res + off);
                    vx += rr.x; vy += rr.y;
                }
                if (OUTH) {
                    __half2 hv = __floats2half2_rn(vx, vy);
                    *(__half2*)((__half*)Cv + off) = hv;
                } else {
                    *(float2*)((float*)Cv + off) = make_float2(vx, vy);
                }
            }
        }
    }
}

// ---------------------------------------------------------------------------
// Offset attention on combined [q|k|v|gate] buffer (stride DQG).
// One warp per (n,h); 4 offset-groups x 8 dim-lanes.
// ---------------------------------------------------------------------------
__global__ void attn_kernel(const __half* __restrict__ qg,
                            const float* __restrict__ pos_bias,
                            __half* __restrict__ y) {
    int warp = (blockIdx.x * blockDim.x + threadIdx.x) >> 5;
    int lane = threadIdx.x & 31;
    int n = warp >> 4;
    int h = warp & 15;
    int j = lane & 7;
    int g = lane >> 3;

    const __half* qrow  = qg + (size_t)n * DQG + h * HDIM + j * 8;
    const __half* kbase = qg + DMODEL + h * HDIM + j * 8;
    const __half* vbase = qg + 2 * DMODEL + h * HDIM + j * 8;
    const __half* gbase = qg + 3 * DMODEL + h * HDIM + j * 8;

    uint4 qv = *(const uint4*)(qrow);
    float2 q0 = h2f2(qv.x), q1 = h2f2(qv.y), q2 = h2f2(qv.z), q3 = h2f2(qv.w);

    const float scale = 0.125f;
    float s[11];

    #pragma unroll
    for (int i = 0; i < 11; i++) {
        int o = i * 4 + g;
        int delta = c_offs[o];
        bool valid = (delta <= n);
        float p = 0.f;
        if (valid) {
            uint4 kv = *(const uint4*)(kbase + (size_t)(n - delta) * DQG);
            float2 k0 = h2f2(kv.x), k1 = h2f2(kv.y), k2 = h2f2(kv.z), k3 = h2f2(kv.w);
            p = q0.x * k0.x + q0.y * k0.y + q1.x * k1.x + q1.y * k1.y
              + q2.x * k2.x + q2.y * k2.y + q3.x * k3.x + q3.y * k3.y;
        }
        p += __shfl_xor_sync(0xffffffffu, p, 1);
        p += __shfl_xor_sync(0xffffffffu, p, 2);
        p += __shfl_xor_sync(0xffffffffu, p, 4);
        s[i] = valid ? p * scale + pos_bias[o * NHEAD + h] : -INFINITY;
    }

    float mx = s[0];
    #pragma unroll
    for (int i = 1; i < 11; i++) mx = fmaxf(mx, s[i]);
    mx = fmaxf(mx, __shfl_xor_sync(0xffffffffu, mx, 8));
    mx = fmaxf(mx, __shfl_xor_sync(0xffffffffu, mx, 16));

    float denom = 0.f;
    #pragma unroll
    for (int i = 0; i < 11; i++) {
        s[i] = __expf(s[i] - mx);      // -inf -> 0
        denom += s[i];
    }
    denom += __shfl_xor_sync(0xffffffffu, denom, 8);
    denom += __shfl_xor_sync(0xffffffffu, denom, 16);

    float acc[8] = {0.f, 0.f, 0.f, 0.f, 0.f, 0.f, 0.f, 0.f};
    #pragma unroll
    for (int i = 0; i < 11; i++) {
        int o = i * 4 + g;
        int delta = c_offs[o];
        if (delta <= n) {
            uint4 vv = *(const uint4*)(vbase + (size_t)(n - delta) * DQG);
            float2 v0 = h2f2(vv.x), v1 = h2f2(vv.y), v2 = h2f2(vv.z), v3 = h2f2(vv.w);
            float w = s[i];
            acc[0] = fmaf(w, v0.x, acc[0]);
            acc[1] = fmaf(w, v0.y, acc[1]);
            acc[2] = fmaf(w, v1.x, acc[2]);
            acc[3] = fmaf(w, v1.y, acc[3]);
            acc[4] = fmaf(w, v2.x, acc[4]);
            acc[5] = fmaf(w, v2.y, acc[5]);
            acc[6] = fmaf(w, v3.x, acc[6]);
            acc[7] = fmaf(w, v3.y, acc[7]);
        }
    }
    #pragma unroll
    for (int d = 0; d < 8; d++) {
        acc[d] += __shfl_xor_sync(0xffffffffu, acc[d], 8);
        acc[d] += __shfl_xor_sync(0xffffffffu, acc[d], 16);
    }

    if (g == 0) {
        float inv = 1.0f / denom;
        uint4 gv = *(const uint4*)(gbase + (size_t)n * DQG);
        float2 g0 = h2f2(gv.x), g1 = h2f2(gv.y), g2 = h2f2(gv.z), g3 = h2f2(gv.w);
        __half2 o0 = __floats2half2_rn(acc[0] * inv * g0.x, acc[1] * inv * g0.y);
        __half2 o1 = __floats2half2_rn(acc[2] * inv * g1.x, acc[3] * inv * g1.y);
        __half2 o2 = __floats2half2_rn(acc[4] * inv * g2.x, acc[5] * inv * g2.y);
        __half2 o3 = __floats2half2_rn(acc[6] * inv * g3.x, acc[7] * inv * g3.y);
        uint4 ov;
        ov.x = *(uint32_t*)&o0; ov.y = *(uint32_t*)&o1;
        ov.z = *(uint32_t*)&o2; ov.w = *(uint32_t*)&o3;
        *(uint4*)(y + (size_t)n * DMODEL + h * HDIM + j * 8) = ov;
    }
}

// ---------------------------------------------------------------------------
// Launch
// ---------------------------------------------------------------------------
extern "C" void kernel_launch(void* const* d_in, const int* in_sizes, int n_in,
                              void* d_out, int out_size) {
    __half *s_xn, *s_qg, *s_y, *s_xn2, *s_h;
    float *s_x1, *s_bqg;
    __half *s_wqg, *s_wout, *s_wfc1, *s_wfc2;
    cudaGetSymbolAddress((void**)&s_xn,  g_xn);
    cudaGetSymbolAddress((void**)&s_qg,  g_qg);
    cudaGetSymbolAddress((void**)&s_y,   g_y);
    cudaGetSymbolAddress((void**)&s_x1,  g_x1);
    cudaGetSymbolAddress((void**)&s_xn2, g_xn2);
    cudaGetSymbolAddress((void**)&s_h,   g_h);
    cudaGetSymbolAddress((void**)&s_wqg, g_wqg);
    cudaGetSymbolAddress((void**)&s_wout,g_wout);
    cudaGetSymbolAddress((void**)&s_wfc1,g_wfc1);
    cudaGetSymbolAddress((void**)&s_wfc2,g_wfc2);
    cudaGetSymbolAddress((void**)&s_bqg, g_bqg);

    const float* x      = (const float*)d_in[0];
    const float* ln1_g  = (const float*)d_in[1];
    const float* ln1_b  = (const float*)d_in[2];
    const float* qkv_w  = (const float*)d_in[3];
    const float* qkv_b  = (const float*)d_in[4];
    const float* gate_w = (const float*)d_in[5];
    const float* gate_b = (const float*)d_in[6];
    const float* out_w  = (const float*)d_in[7];
    const float* out_b  = (const float*)d_in[8];
    const float* pbias  = (const float*)d_in[9];
    const float* ln2_g  = (const float*)d_in[10];
    const float* ln2_b  = (const float*)d_in[11];
    const float* fc1_w  = (const float*)d_in[12];
    const float* fc1_b  = (const float*)d_in[13];
    const float* fc2_w  = (const float*)d_in[14];
    const float* fc2_b  = (const float*)d_in[15];
    float* out = (float*)d_out;

    const int SM_BIG   = 3 * (128 + 256) * 144;  // 165888
    const int SM_SMALL = 3 * (64 + 128) * 144;   //  82944
    cudaFuncSetAttribute(hgemm<128,256,2,4,4,true >, cudaFuncAttributeMaxDynamicSharedMemorySize, SM_BIG);
    cudaFuncSetAttribute(hgemm<128,256,2,4,3,true >, cudaFuncAttributeMaxDynamicSharedMemorySize, SM_BIG);
    cudaFuncSetAttribute(hgemm<64,128,2,2,2,false >, cudaFuncAttributeMaxDynamicSharedMemorySize, SM_SMALL);

    // weight prep: 3072+1024+1024+4096+4096 = 13312 tiles
    prep_kernel<<<13312, dim3(32, 8)>>>(qkv_w, gate_w, out_w, fc1_w, fc2_w);
    bias_cat<<<DQG / 256, 256>>>(qkv_b, gate_b);

    // 1) LN1 -> fp16
    ln_kernel<<<NSEQ, 256>>>(x, ln1_g, ln1_b, s_xn);
    // 2) [qkv|gate] = xn @ wqg + bqg (sigmoid on gate cols)
    hgemm<128,256,2,4,4,true><<<dim3(DQG / 256, NSEQ / 128), 256, SM_BIG>>>(
        s_xn, s_wqg, s_bqg, nullptr, s_qg, DQG, DMODEL);
    // 3) attention (+gate)
    attn_kernel<<<(NSEQ * NHEAD) / 8, 256>>>(s_qg, pbias, s_y);
    // 4) x1 = x + y @ out_w + out_b
    hgemm<64,128,2,2,2,false><<<dim3(DMODEL / 128, NSEQ / 64), 128, SM_SMALL>>>(
        s_y, s_wout, out_b, x, s_x1, DMODEL, DMODEL);
    // 5) LN2 -> fp16
    ln_kernel<<<NSEQ, 256>>>(s_x1, ln2_g, ln2_b, s_xn2);
    // 6) h = gelu(xn2 @ fc1_w + fc1_b)
    hgemm<128,256,2,4,3,true><<<dim3(DFF / 256, NSEQ / 128), 256, SM_BIG>>>(
        s_xn2, s_wfc1, fc1_b, nullptr, s_h, DFF, DMODEL);
    // 7) out = x1 + h @ fc2_w + fc2_b
    hgemm<64,128,2,2,2,false><<<dim3(DMODEL / 128, NSEQ / 64), 128, SM_SMALL>>>(
        s_h, s_wfc2, fc2_b, s_x1, out, DMODEL, DFF);
}

// round 8
// speedup vs baseline: 6.4656x; 1.0770x over previous
#include <cuda_runtime.h>
#include <cuda_fp16.h>
#include <math.h>
#include <stdint.h>

// ---------------------------------------------------------------------------
#define NSEQ 2048
#define DMODEL 1024
#define NHEAD 16
#define HDIM 64
#define DFF 4096
#define NOFF 44
#define D3 (3 * DMODEL)
#define DQG 4096          // qkv + gate combined width

__constant__ int c_offs[NOFF] = {
    0,1,2,3,4,5,6,7,8,9,10,11,12,13,14,15,16,17,18,19,20,21,22,23,24,25,26,27,
    28,29,30,31,32,48,64,96,128,192,256,384,512,768,1024,1536};

// ---------------------------------------------------------------------------
// Scratch
// ---------------------------------------------------------------------------
__device__ __half g_xn [NSEQ * DMODEL];
__device__ __half g_qg [NSEQ * DQG];      // [q|k|v|gate] fp16
__device__ __half g_y  [NSEQ * DMODEL];
__device__ float  g_x1 [NSEQ * DMODEL];
__device__ __half g_xn2[NSEQ * DMODEL];
__device__ __half g_h  [NSEQ * DFF];
__device__ __half g_wqg [DQG * DMODEL];
__device__ __half g_wout[DMODEL * DMODEL];
__device__ __half g_wfc1[DFF * DMODEL];
__device__ __half g_wfc2[DMODEL * DFF];
__device__ float  g_bqg [DQG];

// ---------------------------------------------------------------------------
__device__ __forceinline__ uint32_t smem_u32(const void* p) {
    uint32_t a;
    asm("{ .reg .u64 t; cvta.to.shared.u64 t, %1; cvt.u32.u64 %0, t; }"
        : "=r"(a) : "l"(p));
    return a;
}

#define CPA16(dst, src) \
    asm volatile("cp.async.cg.shared.global [%0], [%1], 16;\n" :: "r"(dst), "l"(src))

#define LDSM_X4(r0, r1, r2, r3, addr) \
    asm volatile("ldmatrix.sync.aligned.m8n8.x4.shared.b16 {%0,%1,%2,%3}, [%4];" \
        : "=r"(r0), "=r"(r1), "=r"(r2), "=r"(r3) : "r"(addr))

__device__ __forceinline__ float2 h2f2(uint32_t u) {
    __half2 h = *(__half2*)&u;
    return __half22float2(h);
}

// ---------------------------------------------------------------------------
// Fused weight prep: all transposes [K,N]fp32 -> [N,K]fp16 in one kernel
// ---------------------------------------------------------------------------
__global__ void prep_kernel(const float* __restrict__ qkv_w,
                            const float* __restrict__ gate_w,
                            const float* __restrict__ out_w,
                            const float* __restrict__ fc1_w,
                            const float* __restrict__ fc2_w) {
    __shared__ float t[32][33];
    int bid = blockIdx.x;
    const float* W; __half* Wt; int K, Nw, b;
    if (bid < 3072)       { b = bid;        W = qkv_w;  Wt = g_wqg;                       K = 1024; Nw = 3072; }
    else if (bid < 4096)  { b = bid - 3072; W = gate_w; Wt = g_wqg + (size_t)3072 * 1024; K = 1024; Nw = 1024; }
    else if (bid < 5120)  { b = bid - 4096; W = out_w;  Wt = g_wout;                      K = 1024; Nw = 1024; }
    else if (bid < 9216)  { b = bid - 5120; W = fc1_w;  Wt = g_wfc1;                      K = 1024; Nw = 4096; }
    else                  { b = bid - 9216; W = fc2_w;  Wt = g_wfc2;                      K = 4096; Nw = 1024; }
    int nx = Nw >> 5;
    int n0 = (b % nx) * 32, k0 = (b / nx) * 32;
    int tx = threadIdx.x, ty = threadIdx.y;
    #pragma unroll
    for (int i = 0; i < 32; i += 8)
        t[ty + i][tx] = W[(size_t)(k0 + ty + i) * Nw + n0 + tx];
    __syncthreads();
    #pragma unroll
    for (int i = 0; i < 32; i += 8)
        Wt[(size_t)(n0 + ty + i) * K + k0 + tx] = __float2half_rn(t[tx][ty + i]);
}

__global__ void bias_cat(const float* __restrict__ qkv_b,
                         const float* __restrict__ gate_b) {
    int i = blockIdx.x * 256 + threadIdx.x;
    if (i < DQG) g_bqg[i] = (i < D3) ? qkv_b[i] : gate_b[i - D3];
}

// ---------------------------------------------------------------------------
// LayerNorm -> fp16
// ---------------------------------------------------------------------------
__global__ void ln_kernel(const float* __restrict__ x,
                          const float* __restrict__ g,
                          const float* __restrict__ b,
                          __half* __restrict__ out) {
    int row = blockIdx.x;
    int tid = threadIdx.x;
    const float4* xr = (const float4*)(x + (size_t)row * DMODEL);
    float4 v = xr[tid];
    float s  = v.x + v.y + v.z + v.w;
    float sq = v.x * v.x + v.y * v.y + v.z * v.z + v.w * v.w;
    #pragma unroll
    for (int o = 16; o > 0; o >>= 1) {
        s  += __shfl_xor_sync(0xffffffffu, s,  o);
        sq += __shfl_xor_sync(0xffffffffu, sq, o);
    }
    __shared__ float sh[16];
    int wid = tid >> 5, lane = tid & 31;
    if (lane == 0) { sh[wid] = s; sh[wid + 8] = sq; }
    __syncthreads();
    float ts = 0.f, tq = 0.f;
    #pragma unroll
    for (int w = 0; w < 8; w++) { ts += sh[w]; tq += sh[w + 8]; }
    float mu  = ts * (1.0f / DMODEL);
    float var = tq * (1.0f / DMODEL) - mu * mu;
    var = var > 0.f ? var : 0.f;
    float rstd = rsqrtf(var + 1e-5f);

    float4 gv = ((const float4*)g)[tid];
    float4 bv = ((const float4*)b)[tid];
    __half2 h0 = __floats2half2_rn((v.x - mu) * rstd * gv.x + bv.x,
                                   (v.y - mu) * rstd * gv.y + bv.y);
    __half2 h1 = __floats2half2_rn((v.z - mu) * rstd * gv.z + bv.z,
                                   (v.w - mu) * rstd * gv.w + bv.w);
    uint2 o;
    o.x = *(uint32_t*)&h0;
    o.y = *(uint32_t*)&h1;
    *(uint2*)(out + (size_t)row * DMODEL + tid * 4) = o;
}

// ---------------------------------------------------------------------------
// fp16 tile loader: ROWS x 64 halves, row stride 144B
// ---------------------------------------------------------------------------
template <int ROWS, int NT>
__device__ __forceinline__ void tile_load(uint32_t dst, const __half* src,
                                          int ldK, int tid) {
    #pragma unroll
    for (int i = 0; i < ROWS * 8 / NT; i++) {
        int c = i * NT + tid;
        int m = c >> 3, q = c & 7;
        CPA16(dst + (uint32_t)(m * 144 + q * 16), src + (size_t)m * ldK + q * 8);
    }
}

// ---------------------------------------------------------------------------
// fp16 GEMM, ldmatrix + 3-stage cp.async, 2 CTAs/SM.
//   EPI 2: +bias+res(fp32)->fp32 | 3: gelu->fp16 | 4: qkv|gate mixed ->fp16
// ---------------------------------------------------------------------------
template <int BM, int BN, int WM, int WN, int EPI, bool OUTH>
__global__ void __launch_bounds__(WM * WN * 32, 2)
hgemm(const __half* __restrict__ A, const __half* __restrict__ Bt,
      const float* __restrict__ bias, const float* __restrict__ res,
      void* __restrict__ Cv, int N, int K) {
    constexpr int NT = WM * WN * 32;
    constexpr int MI = BM / WM / 16;
    constexpr int NI = BN / WN / 8;
    constexpr int NJ = NI / 2;
    constexpr uint32_t ASTAGE = BM * 144;
    constexpr uint32_t BSTAGE = BN * 144;

    extern __shared__ char dsm[];

    const int tid  = threadIdx.x;
    const int warp = tid >> 5, lane = tid & 31;
    const int g    = lane >> 2, t4 = lane & 3;
    const int warpM = (warp / WN) * (BM / WM);
    const int warpN = (warp % WN) * (BN / WN);
    const int rowBase = blockIdx.y * BM;
    const int colBase = blockIdx.x * BN;

    const uint32_t smA = smem_u32(dsm);
    const uint32_t smB = smA + 3 * ASTAGE;
    const uint32_t aLds = smA + (uint32_t)((warpM + (lane & 15)) * 144 + (lane >> 4) * 16);
    const uint32_t bLds = smB + (uint32_t)((warpN + (lane & 15)) * 144 + (lane >> 4) * 16);

    const __half* Ag = A + (size_t)rowBase * K;
    const __half* Bg = Bt + (size_t)colBase * K;

    float acc[MI][NI][4];
    #pragma unroll
    for (int mi = 0; mi < MI; mi++)
        #pragma unroll
        for (int ni = 0; ni < NI; ni++)
            #pragma unroll
            for (int r = 0; r < 4; r++) acc[mi][ni][r] = 0.f;

    const int KT = K / 64;
    tile_load<BM, NT>(smA, Ag, K, tid);
    tile_load<BN, NT>(smB, Bg, K, tid);
    asm volatile("cp.async.commit_group;\n");
    if (KT > 1) {
        tile_load<BM, NT>(smA + ASTAGE, Ag + 64, K, tid);
        tile_load<BN, NT>(smB + BSTAGE, Bg + 64, K, tid);
        asm volatile("cp.async.commit_group;\n");
    }

    for (int kt = 0; kt < KT; kt++) {
        if (kt + 1 < KT) asm volatile("cp.async.wait_group 1;\n");
        else             asm volatile("cp.async.wait_group 0;\n");
        __syncthreads();

        if (kt + 2 < KT) {
            const uint32_t nb = (uint32_t)((kt + 2) % 3);
            tile_load<BM, NT>(smA + nb * ASTAGE, Ag + (kt + 2) * 64, K, tid);
            tile_load<BN, NT>(smB + nb * BSTAGE, Bg + (kt + 2) * 64, K, tid);
            asm volatile("cp.async.commit_group;\n");
        }

        const uint32_t aOff = aLds + (uint32_t)(kt % 3) * ASTAGE;
        const uint32_t bOff = bLds + (uint32_t)(kt % 3) * BSTAGE;
        #pragma unroll
        for (int ks = 0; ks < 4; ks++) {
            uint32_t af[MI][4], bf[NJ][4];
            #pragma unroll
            for (int mi = 0; mi < MI; mi++)
                LDSM_X4(af[mi][0], af[mi][1], af[mi][2], af[mi][3],
                        aOff + (uint32_t)(mi * 16 * 144 + ks * 32));
            #pragma unroll
            for (int nj = 0; nj < NJ; nj++)
                LDSM_X4(bf[nj][0], bf[nj][1], bf[nj][2], bf[nj][3],
                        bOff + (uint32_t)(nj * 16 * 144 + ks * 32));
            #pragma unroll
            for (int mi = 0; mi < MI; mi++)
                #pragma unroll
                for (int nj = 0; nj < NJ; nj++) {
                    asm volatile(
                        "mma.sync.aligned.m16n8k16.row.col.f32.f16.f16.f32 "
                        "{%0,%1,%2,%3}, {%4,%5,%6,%7}, {%8,%9}, {%0,%1,%2,%3};\n"
                        : "+f"(acc[mi][2*nj][0]), "+f"(acc[mi][2*nj][1]),
                          "+f"(acc[mi][2*nj][2]), "+f"(acc[mi][2*nj][3])
                        : "r"(af[mi][0]), "r"(af[mi][1]), "r"(af[mi][2]), "r"(af[mi][3]),
                          "r"(bf[nj][0]), "r"(bf[nj][2]));
                    asm volatile(
                        "mma.sync.aligned.m16n8k16.row.col.f32.f16.f16.f32 "
                        "{%0,%1,%2,%3}, {%4,%5,%6,%7}, {%8,%9}, {%0,%1,%2,%3};\n"
                        : "+f"(acc[mi][2*nj+1][0]), "+f"(acc[mi][2*nj+1][1]),
                          "+f"(acc[mi][2*nj+1][2]), "+f"(acc[mi][2*nj+1][3])
                        : "r"(af[mi][0]), "r"(af[mi][1]), "r"(af[mi][2]), "r"(af[mi][3]),
                          "r"(bf[nj][1]), "r"(bf[nj][3]));
                }
        }
        __syncthreads();
    }

    // epilogue
    const bool sig = (EPI == 4) && (colBase >= D3);
    #pragma unroll
    for (int mi = 0; mi < MI; mi++) {
        #pragma unroll
        for (int ni = 0; ni < NI; ni++) {
            int row = rowBase + warpM + mi * 16 + g;
            int col = colBase + warpN + ni * 8 + t4 * 2;
            float b0 = bias[col], b1 = bias[col + 1];
            #pragma unroll
            for (int hh = 0; hh < 2; hh++) {
                int r = row + hh * 8;
                float vx = acc[mi][ni][hh * 2 + 0] + b0;
                float vy = acc[mi][ni][hh * 2 + 1] + b1;
                if (EPI == 3) {
                    vx = 0.5f * vx * (1.0f + erff(vx * 0.70710678118654752f));
                    vy = 0.5f * vy * (1.0f + erff(vy * 0.70710678118654752f));
                } else if (EPI == 4) {
                    if (sig) {
                        vx = 1.0f / (1.0f + __expf(-vx));
                        vy = 1.0f / (1.0f + __expf(-vy));
                    }
                }
                size_t off = (size_t)r * N + col;
                if (EPI == 2) {
                    float2 rr = *(const float2*)(res + off);
                    vx += rr.x; vy += rr.y;
                }
                if (OUTH) {
                    __half2 hv = __floats2half2_rn(vx, vy);
                    *(__half2*)((__half*)Cv + off) = hv;
                } else {
                    *(float2*)((float*)Cv + off) = make_float2(vx, vy);
                }
            }
        }
    }
}

// ---------------------------------------------------------------------------
// Offset attention on combined [q|k|v|gate] buffer (stride DQG).
// ---------------------------------------------------------------------------
__global__ void attn_kernel(const __half* __restrict__ qg,
                            const float* __restrict__ pos_bias,
                            __half* __restrict__ y) {
    int warp = (blockIdx.x * blockDim.x + threadIdx.x) >> 5;
    int lane = threadIdx.x & 31;
    int n = warp >> 4;
    int h = warp & 15;
    int j = lane & 7;
    int g = lane >> 3;

    const __half* qrow  = qg + (size_t)n * DQG + h * HDIM + j * 8;
    const __half* kbase = qg + DMODEL + h * HDIM + j * 8;
    const __half* vbase = qg + 2 * DMODEL + h * HDIM + j * 8;
    const __half* gbase = qg + 3 * DMODEL + h * HDIM + j * 8;

    uint4 qv = *(const uint4*)(qrow);
    float2 q0 = h2f2(qv.x), q1 = h2f2(qv.y), q2 = h2f2(qv.z), q3 = h2f2(qv.w);

    const float scale = 0.125f;
    float s[11];

    #pragma unroll
    for (int i = 0; i < 11; i++) {
        int o = i * 4 + g;
        int delta = c_offs[o];
        bool valid = (delta <= n);
        float p = 0.f;
        if (valid) {
            uint4 kv = *(const uint4*)(kbase + (size_t)(n - delta) * DQG);
            float2 k0 = h2f2(kv.x), k1 = h2f2(kv.y), k2 = h2f2(kv.z), k3 = h2f2(kv.w);
            p = q0.x * k0.x + q0.y * k0.y + q1.x * k1.x + q1.y * k1.y
              + q2.x * k2.x + q2.y * k2.y + q3.x * k3.x + q3.y * k3.y;
        }
        p += __shfl_xor_sync(0xffffffffu, p, 1);
        p += __shfl_xor_sync(0xffffffffu, p, 2);
        p += __shfl_xor_sync(0xffffffffu, p, 4);
        s[i] = valid ? p * scale + pos_bias[o * NHEAD + h] : -INFINITY;
    }

    float mx = s[0];
    #pragma unroll
    for (int i = 1; i < 11; i++) mx = fmaxf(mx, s[i]);
    mx = fmaxf(mx, __shfl_xor_sync(0xffffffffu, mx, 8));
    mx = fmaxf(mx, __shfl_xor_sync(0xffffffffu, mx, 16));

    float denom = 0.f;
    #pragma unroll
    for (int i = 0; i < 11; i++) {
        s[i] = __expf(s[i] - mx);
        denom += s[i];
    }
    denom += __shfl_xor_sync(0xffffffffu, denom, 8);
    denom += __shfl_xor_sync(0xffffffffu, denom, 16);

    float acc[8] = {0.f, 0.f, 0.f, 0.f, 0.f, 0.f, 0.f, 0.f};
    #pragma unroll
    for (int i = 0; i < 11; i++) {
        int o = i * 4 + g;
        int delta = c_offs[o];
        if (delta <= n) {
            uint4 vv = *(const uint4*)(vbase + (size_t)(n - delta) * DQG);
            float2 v0 = h2f2(vv.x), v1 = h2f2(vv.y), v2 = h2f2(vv.z), v3 = h2f2(vv.w);
            float w = s[i];
            acc[0] = fmaf(w, v0.x, acc[0]);
            acc[1] = fmaf(w, v0.y, acc[1]);
            acc[2] = fmaf(w, v1.x, acc[2]);
            acc[3] = fmaf(w, v1.y, acc[3]);
            acc[4] = fmaf(w, v2.x, acc[4]);
            acc[5] = fmaf(w, v2.y, acc[5]);
            acc[6] = fmaf(w, v3.x, acc[6]);
            acc[7] = fmaf(w, v3.y, acc[7]);
        }
    }
    #pragma unroll
    for (int d = 0; d < 8; d++) {
        acc[d] += __shfl_xor_sync(0xffffffffu, acc[d], 8);
        acc[d] += __shfl_xor_sync(0xffffffffu, acc[d], 16);
    }

    if (g == 0) {
        float inv = 1.0f / denom;
        uint4 gv = *(const uint4*)(gbase + (size_t)n * DQG);
        float2 g0 = h2f2(gv.x), g1 = h2f2(gv.y), g2 = h2f2(gv.z), g3 = h2f2(gv.w);
        __half2 o0 = __floats2half2_rn(acc[0] * inv * g0.x, acc[1] * inv * g0.y);
        __half2 o1 = __floats2half2_rn(acc[2] * inv * g1.x, acc[3] * inv * g1.y);
        __half2 o2 = __floats2half2_rn(acc[4] * inv * g2.x, acc[5] * inv * g2.y);
        __half2 o3 = __floats2half2_rn(acc[6] * inv * g3.x, acc[7] * inv * g3.y);
        uint4 ov;
        ov.x = *(uint32_t*)&o0; ov.y = *(uint32_t*)&o1;
        ov.z = *(uint32_t*)&o2; ov.w = *(uint32_t*)&o3;
        *(uint4*)(y + (size_t)n * DMODEL + h * HDIM + j * 8) = ov;
    }
}

// ---------------------------------------------------------------------------
// Launch
// ---------------------------------------------------------------------------
extern "C" void kernel_launch(void* const* d_in, const int* in_sizes, int n_in,
                              void* d_out, int out_size) {
    __half *s_xn, *s_qg, *s_y, *s_xn2, *s_h;
    float *s_x1, *s_bqg;
    __half *s_wqg, *s_wout, *s_wfc1, *s_wfc2;
    cudaGetSymbolAddress((void**)&s_xn,  g_xn);
    cudaGetSymbolAddress((void**)&s_qg,  g_qg);
    cudaGetSymbolAddress((void**)&s_y,   g_y);
    cudaGetSymbolAddress((void**)&s_x1,  g_x1);
    cudaGetSymbolAddress((void**)&s_xn2, g_xn2);
    cudaGetSymbolAddress((void**)&s_h,   g_h);
    cudaGetSymbolAddress((void**)&s_wqg, g_wqg);
    cudaGetSymbolAddress((void**)&s_wout,g_wout);
    cudaGetSymbolAddress((void**)&s_wfc1,g_wfc1);
    cudaGetSymbolAddress((void**)&s_wfc2,g_wfc2);
    cudaGetSymbolAddress((void**)&s_bqg, g_bqg);

    const float* x      = (const float*)d_in[0];
    const float* ln1_g  = (const float*)d_in[1];
    const float* ln1_b  = (const float*)d_in[2];
    const float* qkv_w  = (const float*)d_in[3];
    const float* qkv_b  = (const float*)d_in[4];
    const float* gate_w = (const float*)d_in[5];
    const float* gate_b = (const float*)d_in[6];
    const float* out_w  = (const float*)d_in[7];
    const float* out_b  = (const float*)d_in[8];
    const float* pbias  = (const float*)d_in[9];
    const float* ln2_g  = (const float*)d_in[10];
    const float* ln2_b  = (const float*)d_in[11];
    const float* fc1_w  = (const float*)d_in[12];
    const float* fc1_b  = (const float*)d_in[13];
    const float* fc2_w  = (const float*)d_in[14];
    const float* fc2_b  = (const float*)d_in[15];
    float* out = (float*)d_out;

    const int SM_MED   = 3 * (128 + 128) * 144;  // 110592 -> 2 CTAs/SM
    const int SM_SMALL = 3 * (64 + 128) * 144;   //  82944 -> 2 CTAs/SM
    cudaFuncSetAttribute(hgemm<128,128,4,2,4,true >, cudaFuncAttributeMaxDynamicSharedMemorySize, SM_MED);
    cudaFuncSetAttribute(hgemm<128,128,4,2,3,true >, cudaFuncAttributeMaxDynamicSharedMemorySize, SM_MED);
    cudaFuncSetAttribute(hgemm<64,128,2,2,2,false >, cudaFuncAttributeMaxDynamicSharedMemorySize, SM_SMALL);

    prep_kernel<<<13312, dim3(32, 8)>>>(qkv_w, gate_w, out_w, fc1_w, fc2_w);
    bias_cat<<<DQG / 256, 256>>>(qkv_b, gate_b);

    // 1) LN1 -> fp16
    ln_kernel<<<NSEQ, 256>>>(x, ln1_g, ln1_b, s_xn);
    // 2) [qkv|gate] = xn @ wqg + bqg (sigmoid on gate cols)
    hgemm<128,128,4,2,4,true><<<dim3(DQG / 128, NSEQ / 128), 256, SM_MED>>>(
        s_xn, s_wqg, s_bqg, nullptr, s_qg, DQG, DMODEL);
    // 3) attention (+gate)
    attn_kernel<<<(NSEQ * NHEAD) / 8, 256>>>(s_qg, pbias, s_y);
    // 4) x1 = x + y @ out_w + out_b
    hgemm<64,128,2,2,2,false><<<dim3(DMODEL / 128, NSEQ / 64), 128, SM_SMALL>>>(
        s_y, s_wout, out_b, x, s_x1, DMODEL, DMODEL);
    // 5) LN2 -> fp16
    ln_kernel<<<NSEQ, 256>>>(s_x1, ln2_g, ln2_b, s_xn2);
    // 6) h = gelu(xn2 @ fc1_w + fc1_b)
    hgemm<128,128,4,2,3,true><<<dim3(DFF / 128, NSEQ / 128), 256, SM_MED>>>(
        s_xn2, s_wfc1, fc1_b, nullptr, s_h, DFF, DMODEL);
    // 7) out = x1 + h @ fc2_w + fc2_b
    hgemm<64,128,2,2,2,false><<<dim3(DMODEL / 128, NSEQ / 64), 128, SM_SMALL>>>(
        s_h, s_wfc2, fc2_b, s_x1, out, DMODEL, DFF);
}

// round 9
// speedup vs baseline: 6.6297x; 1.0254x over previous
#include <cuda_runtime.h>
#include <cuda_fp16.h>
#include <math.h>
#include <stdint.h>

// ---------------------------------------------------------------------------
#define NSEQ 2048
#define DMODEL 1024
#define NHEAD 16
#define HDIM 64
#define DFF 4096
#define NOFF 44
#define D3 (3 * DMODEL)
#define DQG 4096          // qkv + gate combined width

__constant__ int c_offs[NOFF] = {
    0,1,2,3,4,5,6,7,8,9,10,11,12,13,14,15,16,17,18,19,20,21,22,23,24,25,26,27,
    28,29,30,31,32,48,64,96,128,192,256,384,512,768,1024,1536};

// ---------------------------------------------------------------------------
// Scratch
// ---------------------------------------------------------------------------
__device__ __half g_xn [NSEQ * DMODEL];
__device__ __half g_qg [NSEQ * DQG];      // [q|k|v|gate] fp16
__device__ __half g_y  [NSEQ * DMODEL];
__device__ float  g_x1 [NSEQ * DMODEL];
__device__ __half g_xn2[NSEQ * DMODEL];
__device__ __half g_h  [NSEQ * DFF];
__device__ __half g_wqg [DQG * DMODEL];
__device__ __half g_wout[DMODEL * DMODEL];
__device__ __half g_wfc1[DFF * DMODEL];
__device__ __half g_wfc2[DMODEL * DFF];
__device__ float  g_bqg [DQG];

// ---------------------------------------------------------------------------
__device__ __forceinline__ uint32_t smem_u32(const void* p) {
    uint32_t a;
    asm("{ .reg .u64 t; cvta.to.shared.u64 t, %1; cvt.u32.u64 %0, t; }"
        : "=r"(a) : "l"(p));
    return a;
}

#define CPA16(dst, src) \
    asm volatile("cp.async.cg.shared.global [%0], [%1], 16;\n" :: "r"(dst), "l"(src))

#define LDSM_X4(r0, r1, r2, r3, addr) \
    asm volatile("ldmatrix.sync.aligned.m8n8.x4.shared.b16 {%0,%1,%2,%3}, [%4];" \
        : "=r"(r0), "=r"(r1), "=r"(r2), "=r"(r3) : "r"(addr))

__device__ __forceinline__ float2 h2f2(uint32_t u) {
    __half2 h = *(__half2*)&u;
    return __half22float2(h);
}

// ---------------------------------------------------------------------------
// Fused weight prep: all transposes [K,N]fp32 -> [N,K]fp16 in one kernel
// ---------------------------------------------------------------------------
__global__ void prep_kernel(const float* __restrict__ qkv_w,
                            const float* __restrict__ gate_w,
                            const float* __restrict__ out_w,
                            const float* __restrict__ fc1_w,
                            const float* __restrict__ fc2_w) {
    __shared__ float t[32][33];
    int bid = blockIdx.x;
    const float* W; __half* Wt; int K, Nw, b;
    if (bid < 3072)       { b = bid;        W = qkv_w;  Wt = g_wqg;                       K = 1024; Nw = 3072; }
    else if (bid < 4096)  { b = bid - 3072; W = gate_w; Wt = g_wqg + (size_t)3072 * 1024; K = 1024; Nw = 1024; }
    else if (bid < 5120)  { b = bid - 4096; W = out_w;  Wt = g_wout;                      K = 1024; Nw = 1024; }
    else if (bid < 9216)  { b = bid - 5120; W = fc1_w;  Wt = g_wfc1;                      K = 1024; Nw = 4096; }
    else                  { b = bid - 9216; W = fc2_w;  Wt = g_wfc2;                      K = 4096; Nw = 1024; }
    int nx = Nw >> 5;
    int n0 = (b % nx) * 32, k0 = (b / nx) * 32;
    int tx = threadIdx.x, ty = threadIdx.y;
    #pragma unroll
    for (int i = 0; i < 32; i += 8)
        t[ty + i][tx] = W[(size_t)(k0 + ty + i) * Nw + n0 + tx];
    __syncthreads();
    #pragma unroll
    for (int i = 0; i < 32; i += 8)
        Wt[(size_t)(n0 + ty + i) * K + k0 + tx] = __float2half_rn(t[tx][ty + i]);
}

__global__ void bias_cat(const float* __restrict__ qkv_b,
                         const float* __restrict__ gate_b) {
    int i = blockIdx.x * 256 + threadIdx.x;
    if (i < DQG) g_bqg[i] = (i < D3) ? qkv_b[i] : gate_b[i - D3];
}

// ---------------------------------------------------------------------------
// LayerNorm -> fp16
// ---------------------------------------------------------------------------
__global__ void ln_kernel(const float* __restrict__ x,
                          const float* __restrict__ g,
                          const float* __restrict__ b,
                          __half* __restrict__ out) {
    int row = blockIdx.x;
    int tid = threadIdx.x;
    const float4* xr = (const float4*)(x + (size_t)row * DMODEL);
    float4 v = xr[tid];
    float s  = v.x + v.y + v.z + v.w;
    float sq = v.x * v.x + v.y * v.y + v.z * v.z + v.w * v.w;
    #pragma unroll
    for (int o = 16; o > 0; o >>= 1) {
        s  += __shfl_xor_sync(0xffffffffu, s,  o);
        sq += __shfl_xor_sync(0xffffffffu, sq, o);
    }
    __shared__ float sh[16];
    int wid = tid >> 5, lane = tid & 31;
    if (lane == 0) { sh[wid] = s; sh[wid + 8] = sq; }
    __syncthreads();
    float ts = 0.f, tq = 0.f;
    #pragma unroll
    for (int w = 0; w < 8; w++) { ts += sh[w]; tq += sh[w + 8]; }
    float mu  = ts * (1.0f / DMODEL);
    float var = tq * (1.0f / DMODEL) - mu * mu;
    var = var > 0.f ? var : 0.f;
    float rstd = rsqrtf(var + 1e-5f);

    float4 gv = ((const float4*)g)[tid];
    float4 bv = ((const float4*)b)[tid];
    __half2 h0 = __floats2half2_rn((v.x - mu) * rstd * gv.x + bv.x,
                                   (v.y - mu) * rstd * gv.y + bv.y);
    __half2 h1 = __floats2half2_rn((v.z - mu) * rstd * gv.z + bv.z,
                                   (v.w - mu) * rstd * gv.w + bv.w);
    uint2 o;
    o.x = *(uint32_t*)&h0;
    o.y = *(uint32_t*)&h1;
    *(uint2*)(out + (size_t)row * DMODEL + tid * 4) = o;
}

// ---------------------------------------------------------------------------
// fp16 tile loader: ROWS x 64 halves, row stride 144B
// ---------------------------------------------------------------------------
template <int ROWS, int NT>
__device__ __forceinline__ void tile_load(uint32_t dst, const __half* src,
                                          int ldK, int tid) {
    #pragma unroll
    for (int i = 0; i < ROWS * 8 / NT; i++) {
        int c = i * NT + tid;
        int m = c >> 3, q = c & 7;
        CPA16(dst + (uint32_t)(m * 144 + q * 16), src + (size_t)m * ldK + q * 8);
    }
}

// ---------------------------------------------------------------------------
// fp16 GEMM, warp tile 32x32, 8 warps, 2-stage cp.async, 4 CTAs/SM.
//   EPI 2: +bias+res(fp32)->fp32 | 3: gelu->fp16 | 4: qkv|gate mixed ->fp16
// ---------------------------------------------------------------------------
template <int BM, int BN, int WM, int WN, int EPI, bool OUTH>
__global__ void __launch_bounds__(WM * WN * 32, 4)
hgemm(const __half* __restrict__ A, const __half* __restrict__ Bt,
      const float* __restrict__ bias, const float* __restrict__ res,
      void* __restrict__ Cv, int N, int K) {
    constexpr int NT = WM * WN * 32;
    constexpr int MI = BM / WM / 16;
    constexpr int NI = BN / WN / 8;
    constexpr int NJ = NI / 2;
    constexpr uint32_t ASTAGE = BM * 144;
    constexpr uint32_t BSTAGE = BN * 144;

    extern __shared__ char dsm[];

    const int tid  = threadIdx.x;
    const int warp = tid >> 5, lane = tid & 31;
    const int g    = lane >> 2, t4 = lane & 3;
    const int warpM = (warp / WN) * (BM / WM);
    const int warpN = (warp % WN) * (BN / WN);
    const int rowBase = blockIdx.y * BM;
    const int colBase = blockIdx.x * BN;

    const uint32_t smA = smem_u32(dsm);
    const uint32_t smB = smA + 2 * ASTAGE;
    const uint32_t aLds = smA + (uint32_t)((warpM + (lane & 15)) * 144 + (lane >> 4) * 16);
    const uint32_t bLds = smB + (uint32_t)((warpN + (lane & 15)) * 144 + (lane >> 4) * 16);

    const __half* Ag = A + (size_t)rowBase * K;
    const __half* Bg = Bt + (size_t)colBase * K;

    float acc[MI][NI][4];
    #pragma unroll
    for (int mi = 0; mi < MI; mi++)
        #pragma unroll
        for (int ni = 0; ni < NI; ni++)
            #pragma unroll
            for (int r = 0; r < 4; r++) acc[mi][ni][r] = 0.f;

    const int KT = K / 64;
    // prologue: stage 0
    tile_load<BM, NT>(smA, Ag, K, tid);
    tile_load<BN, NT>(smB, Bg, K, tid);
    asm volatile("cp.async.commit_group;\n");

    for (int kt = 0; kt < KT; kt++) {
        asm volatile("cp.async.wait_group 0;\n");
        __syncthreads();

        // prefetch next stage into the other buffer
        if (kt + 1 < KT) {
            const uint32_t nb = (uint32_t)((kt + 1) & 1);
            tile_load<BM, NT>(smA + nb * ASTAGE, Ag + (kt + 1) * 64, K, tid);
            tile_load<BN, NT>(smB + nb * BSTAGE, Bg + (kt + 1) * 64, K, tid);
            asm volatile("cp.async.commit_group;\n");
        }

        const uint32_t aOff = aLds + (uint32_t)(kt & 1) * ASTAGE;
        const uint32_t bOff = bLds + (uint32_t)(kt & 1) * BSTAGE;
        #pragma unroll
        for (int ks = 0; ks < 4; ks++) {
            uint32_t af[MI][4], bf[NJ][4];
            #pragma unroll
            for (int mi = 0; mi < MI; mi++)
                LDSM_X4(af[mi][0], af[mi][1], af[mi][2], af[mi][3],
                        aOff + (uint32_t)(mi * 16 * 144 + ks * 32));
            #pragma unroll
            for (int nj = 0; nj < NJ; nj++)
                LDSM_X4(bf[nj][0], bf[nj][1], bf[nj][2], bf[nj][3],
                        bOff + (uint32_t)(nj * 16 * 144 + ks * 32));
            #pragma unroll
            for (int mi = 0; mi < MI; mi++)
                #pragma unroll
                for (int nj = 0; nj < NJ; nj++) {
                    asm volatile(
                        "mma.sync.aligned.m16n8k16.row.col.f32.f16.f16.f32 "
                        "{%0,%1,%2,%3}, {%4,%5,%6,%7}, {%8,%9}, {%0,%1,%2,%3};\n"
                        : "+f"(acc[mi][2*nj][0]), "+f"(acc[mi][2*nj][1]),
                          "+f"(acc[mi][2*nj][2]), "+f"(acc[mi][2*nj][3])
                        : "r"(af[mi][0]), "r"(af[mi][1]), "r"(af[mi][2]), "r"(af[mi][3]),
                          "r"(bf[nj][0]), "r"(bf[nj][2]));
                    asm volatile(
                        "mma.sync.aligned.m16n8k16.row.col.f32.f16.f16.f32 "
                        "{%0,%1,%2,%3}, {%4,%5,%6,%7}, {%8,%9}, {%0,%1,%2,%3};\n"
                        : "+f"(acc[mi][2*nj+1][0]), "+f"(acc[mi][2*nj+1][1]),
                          "+f"(acc[mi][2*nj+1][2]), "+f"(acc[mi][2*nj+1][3])
                        : "r"(af[mi][0]), "r"(af[mi][1]), "r"(af[mi][2]), "r"(af[mi][3]),
                          "r"(bf[nj][1]), "r"(bf[nj][3]));
                }
        }
        __syncthreads();
    }

    // epilogue
    const bool sig = (EPI == 4) && (colBase >= D3);
    #pragma unroll
    for (int mi = 0; mi < MI; mi++) {
        #pragma unroll
        for (int ni = 0; ni < NI; ni++) {
            int row = rowBase + warpM + mi * 16 + g;
            int col = colBase + warpN + ni * 8 + t4 * 2;
            float b0 = bias[col], b1 = bias[col + 1];
            #pragma unroll
            for (int hh = 0; hh < 2; hh++) {
                int r = row + hh * 8;
                float vx = acc[mi][ni][hh * 2 + 0] + b0;
                float vy = acc[mi][ni][hh * 2 + 1] + b1;
                if (EPI == 3) {
                    vx = 0.5f * vx * (1.0f + erff(vx * 0.70710678118654752f));
                    vy = 0.5f * vy * (1.0f + erff(vy * 0.70710678118654752f));
                } else if (EPI == 4) {
                    if (sig) {
                        vx = 1.0f / (1.0f + __expf(-vx));
                        vy = 1.0f / (1.0f + __expf(-vy));
                    }
                }
                size_t off = (size_t)r * N + col;
                if (EPI == 2) {
                    float2 rr = *(const float2*)(res + off);
                    vx += rr.x; vy += rr.y;
                }
                if (OUTH) {
                    __half2 hv = __floats2half2_rn(vx, vy);
                    *(__half2*)((__half*)Cv + off) = hv;
                } else {
                    *(float2*)((float*)Cv + off) = make_float2(vx, vy);
                }
            }
        }
    }
}

// ---------------------------------------------------------------------------
// Offset attention on combined [q|k|v|gate] buffer (stride DQG).
// Warp mapping: warp_global = h*2048 + n  (consecutive n share a CTA/SM for
// L1 line reuse across shifted K/V rows). 4 offset-groups x 8 dim-lanes.
// ---------------------------------------------------------------------------
__global__ void attn_kernel(const __half* __restrict__ qg,
                            const float* __restrict__ pos_bias,
                            __half* __restrict__ y) {
    int warp = blockIdx.x * (blockDim.x >> 5) + (threadIdx.x >> 5);
    int lane = threadIdx.x & 31;
    int h = warp >> 11;       // warp / 2048
    int n = warp & 2047;
    int j = lane & 7;
    int g = lane >> 3;

    const __half* qrow  = qg + (size_t)n * DQG + h * HDIM + j * 8;
    const __half* kbase = qg + DMODEL + h * HDIM + j * 8;
    const __half* vbase = qg + 2 * DMODEL + h * HDIM + j * 8;
    const __half* gbase = qg + 3 * DMODEL + h * HDIM + j * 8;

    uint4 qv = *(const uint4*)(qrow);
    float2 q0 = h2f2(qv.x), q1 = h2f2(qv.y), q2 = h2f2(qv.z), q3 = h2f2(qv.w);

    const float scale = 0.125f;
    float s[11];

    #pragma unroll
    for (int i = 0; i < 11; i++) {
        int o = i * 4 + g;
        int delta = c_offs[o];
        bool valid = (delta <= n);
        float p = 0.f;
        if (valid) {
            uint4 kv = *(const uint4*)(kbase + (size_t)(n - delta) * DQG);
            float2 k0 = h2f2(kv.x), k1 = h2f2(kv.y), k2 = h2f2(kv.z), k3 = h2f2(kv.w);
            p = q0.x * k0.x + q0.y * k0.y + q1.x * k1.x + q1.y * k1.y
              + q2.x * k2.x + q2.y * k2.y + q3.x * k3.x + q3.y * k3.y;
        }
        p += __shfl_xor_sync(0xffffffffu, p, 1);
        p += __shfl_xor_sync(0xffffffffu, p, 2);
        p += __shfl_xor_sync(0xffffffffu, p, 4);
        s[i] = valid ? p * scale + pos_bias[o * NHEAD + h] : -INFINITY;
    }

    float mx = s[0];
    #pragma unroll
    for (int i = 1; i < 11; i++) mx = fmaxf(mx, s[i]);
    mx = fmaxf(mx, __shfl_xor_sync(0xffffffffu, mx, 8));
    mx = fmaxf(mx, __shfl_xor_sync(0xffffffffu, mx, 16));

    float denom = 0.f;
    #pragma unroll
    for (int i = 0; i < 11; i++) {
        s[i] = __expf(s[i] - mx);
        denom += s[i];
    }
    denom += __shfl_xor_sync(0xffffffffu, denom, 8);
    denom += __shfl_xor_sync(0xffffffffu, denom, 16);

    float acc[8] = {0.f, 0.f, 0.f, 0.f, 0.f, 0.f, 0.f, 0.f};
    #pragma unroll
    for (int i = 0; i < 11; i++) {
        int o = i * 4 + g;
        int delta = c_offs[o];
        if (delta <= n) {
            uint4 vv = *(const uint4*)(vbase + (size_t)(n - delta) * DQG);
            float2 v0 = h2f2(vv.x), v1 = h2f2(vv.y), v2 = h2f2(vv.z), v3 = h2f2(vv.w);
            float w = s[i];
            acc[0] = fmaf(w, v0.x, acc[0]);
            acc[1] = fmaf(w, v0.y, acc[1]);
            acc[2] = fmaf(w, v1.x, acc[2]);
            acc[3] = fmaf(w, v1.y, acc[3]);
            acc[4] = fmaf(w, v2.x, acc[4]);
            acc[5] = fmaf(w, v2.y, acc[5]);
            acc[6] = fmaf(w, v3.x, acc[6]);
            acc[7] = fmaf(w, v3.y, acc[7]);
        }
    }
    #pragma unroll
    for (int d = 0; d < 8; d++) {
        acc[d] += __shfl_xor_sync(0xffffffffu, acc[d], 8);
        acc[d] += __shfl_xor_sync(0xffffffffu, acc[d], 16);
    }

    if (g == 0) {
        float inv = 1.0f / denom;
        uint4 gv = *(const uint4*)(gbase + (size_t)n * DQG);
        float2 g0 = h2f2(gv.x), g1 = h2f2(gv.y), g2 = h2f2(gv.z), g3 = h2f2(gv.w);
        __half2 o0 = __floats2half2_rn(acc[0] * inv * g0.x, acc[1] * inv * g0.y);
        __half2 o1 = __floats2half2_rn(acc[2] * inv * g1.x, acc[3] * inv * g1.y);
        __half2 o2 = __floats2half2_rn(acc[4] * inv * g2.x, acc[5] * inv * g2.y);
        __half2 o3 = __floats2half2_rn(acc[6] * inv * g3.x, acc[7] * inv * g3.y);
        uint4 ov;
        ov.x = *(uint32_t*)&o0; ov.y = *(uint32_t*)&o1;
        ov.z = *(uint32_t*)&o2; ov.w = *(uint32_t*)&o3;
        *(uint4*)(y + (size_t)n * DMODEL + h * HDIM + j * 8) = ov;
    }
}

// ---------------------------------------------------------------------------
// Launch
// ---------------------------------------------------------------------------
extern "C" void kernel_launch(void* const* d_in, const int* in_sizes, int n_in,
                              void* d_out, int out_size) {
    __half *s_xn, *s_qg, *s_y, *s_xn2, *s_h;
    float *s_x1, *s_bqg;
    __half *s_wqg, *s_wout, *s_wfc1, *s_wfc2;
    cudaGetSymbolAddress((void**)&s_xn,  g_xn);
    cudaGetSymbolAddress((void**)&s_qg,  g_qg);
    cudaGetSymbolAddress((void**)&s_y,   g_y);
    cudaGetSymbolAddress((void**)&s_x1,  g_x1);
    cudaGetSymbolAddress((void**)&s_xn2, g_xn2);
    cudaGetSymbolAddress((void**)&s_h,   g_h);
    cudaGetSymbolAddress((void**)&s_wqg, g_wqg);
    cudaGetSymbolAddress((void**)&s_wout,g_wout);
    cudaGetSymbolAddress((void**)&s_wfc1,g_wfc1);
    cudaGetSymbolAddress((void**)&s_wfc2,g_wfc2);
    cudaGetSymbolAddress((void**)&s_bqg, g_bqg);

    const float* x      = (const float*)d_in[0];
    const float* ln1_g  = (const float*)d_in[1];
    const float* ln1_b  = (const float*)d_in[2];
    const float* qkv_w  = (const float*)d_in[3];
    const float* qkv_b  = (const float*)d_in[4];
    const float* gate_w = (const float*)d_in[5];
    const float* gate_b = (const float*)d_in[6];
    const float* out_w  = (const float*)d_in[7];
    const float* out_b  = (const float*)d_in[8];
    const float* pbias  = (const float*)d_in[9];
    const float* ln2_g  = (const float*)d_in[10];
    const float* ln2_b  = (const float*)d_in[11];
    const float* fc1_w  = (const float*)d_in[12];
    const float* fc1_b  = (const float*)d_in[13];
    const float* fc2_w  = (const float*)d_in[14];
    const float* fc2_b  = (const float*)d_in[15];
    float* out = (float*)d_out;

    // 2-stage smem: 2*(64+128)*144 = 55296 B -> 4 CTAs/SM
    const int SM2 = 2 * (64 + 128) * 144;
    cudaFuncSetAttribute(hgemm<64,128,2,4,4,true >, cudaFuncAttributeMaxDynamicSharedMemorySize, SM2);
    cudaFuncSetAttribute(hgemm<64,128,2,4,3,true >, cudaFuncAttributeMaxDynamicSharedMemorySize, SM2);
    cudaFuncSetAttribute(hgemm<64,128,2,4,2,false>, cudaFuncAttributeMaxDynamicSharedMemorySize, SM2);

    prep_kernel<<<13312, dim3(32, 8)>>>(qkv_w, gate_w, out_w, fc1_w, fc2_w);
    bias_cat<<<DQG / 256, 256>>>(qkv_b, gate_b);

    // 1) LN1 -> fp16
    ln_kernel<<<NSEQ, 256>>>(x, ln1_g, ln1_b, s_xn);
    // 2) [qkv|gate] = xn @ wqg + bqg (sigmoid on gate cols)
    hgemm<64,128,2,4,4,true><<<dim3(DQG / 128, NSEQ / 64), 256, SM2>>>(
        s_xn, s_wqg, s_bqg, nullptr, s_qg, DQG, DMODEL);
    // 3) attention (+gate)
    attn_kernel<<<(NSEQ * NHEAD) / 8, 256>>>(s_qg, pbias, s_y);
    // 4) x1 = x + y @ out_w + out_b
    hgemm<64,128,2,4,2,false><<<dim3(DMODEL / 128, NSEQ / 64), 256, SM2>>>(
        s_y, s_wout, out_b, x, s_x1, DMODEL, DMODEL);
    // 5) LN2 -> fp16
    ln_kernel<<<NSEQ, 256>>>(s_x1, ln2_g, ln2_b, s_xn2);
    // 6) h = gelu(xn2 @ fc1_w + fc1_b)
    hgemm<64,128,2,4,3,true><<<dim3(DFF / 128, NSEQ / 64), 256, SM2>>>(
        s_xn2, s_wfc1, fc1_b, nullptr, s_h, DFF, DMODEL);
    // 7) out = x1 + h @ fc2_w + fc2_b
    hgemm<64,128,2,4,2,false><<<dim3(DMODEL / 128, NSEQ / 64), 256, SM2>>>(
        s_h, s_wfc2, fc2_b, s_x1, out, DMODEL, DFF);
}